// round 2
// baseline (speedup 1.0000x reference)
#include <cuda_runtime.h>

#define HD    64
#define LSEQ  2048
#define BATCH 16
#define NTOK  (BATCH * LSEQ)

typedef unsigned long long ull;

// Scratch (device globals: allocation-free)
__device__ float g_h[NTOK * HD];     // post-LN hidden states (8 MB)
__device__ float g_invd[NTOK];       // 1 / (||h||^2 + 1e-6) per token

// ---------------- packed f32x2 helpers (sm_103a) ----------------
__device__ __forceinline__ ull ffma2(ull a, ull b, ull c) {
    ull d;
    asm("fma.rn.f32x2 %0, %1, %2, %3;" : "=l"(d) : "l"(a), "l"(b), "l"(c));
    return d;
}
__device__ __forceinline__ ull fadd2(ull a, ull b) {
    ull d;
    asm("add.rn.f32x2 %0, %1, %2;" : "=l"(d) : "l"(a), "l"(b));
    return d;
}
__device__ __forceinline__ ull fpack2(float lo, float hi) {
    ull d;
    asm("mov.b64 %0, {%1, %2};" : "=l"(d) : "f"(lo), "f"(hi));
    return d;
}
__device__ __forceinline__ void funpack2(ull v, float& lo, float& hi) {
    asm("mov.b64 {%0, %1}, %2;" : "=f"(lo), "=f"(hi) : "l"(v));
}

// ---------------------------------------------------------------
// Phase 1: h = LN(embed[seq] + MLP(embed[seq])), plus inv_denom.
// One warp per token. W1/W2 live in dynamic shared (64 KB).
// ---------------------------------------------------------------
__global__ __launch_bounds__(256) void phase1_kernel(
    const int*   __restrict__ seq,
    const float* __restrict__ embed,
    const float* __restrict__ W1,
    const float* __restrict__ b1,
    const float* __restrict__ W2,
    const float* __restrict__ b2,
    const float* __restrict__ gamma,
    const float* __restrict__ beta)
{
    extern __shared__ float dsm[];
    float* W1s = dsm;            // 64*128
    float* W2s = dsm + 64 * 128; // 128*64

    __shared__ __align__(16) float b1s[128];
    __shared__ float b2s[64], gs[64], bs[64];
    __shared__ __align__(16) float hs[8][64];
    __shared__ __align__(16) float as_[8][128];

    const int tid = threadIdx.x;
    for (int i = tid; i < 64 * 128; i += 256) W1s[i] = W1[i];
    for (int i = tid; i < 128 * 64; i += 256) W2s[i] = W2[i];
    if (tid < 128) b1s[tid] = b1[tid];
    if (tid < 64) { b2s[tid] = b2[tid]; gs[tid] = gamma[tid]; bs[tid] = beta[tid]; }
    __syncthreads();

    const int w    = tid >> 5;
    const int lane = tid & 31;
    const int gw   = blockIdx.x * 8 + w;
    const int nw   = gridDim.x * 8;

    for (int tok = gw; tok < NTOK; tok += nw) {
        const int v = seq[tok];
        const float h0 = embed[v * 64 + lane];
        const float h1 = embed[v * 64 + 32 + lane];
        hs[w][lane]      = h0;
        hs[w][lane + 32] = h1;
        __syncwarp();

        float4 a4 = *(const float4*)&b1s[lane * 4];
        #pragma unroll 16
        for (int j = 0; j < 64; j++) {
            const float  hj = hs[w][j];
            const float4 w4 = *(const float4*)&W1s[j * 128 + lane * 4];
            a4.x = fmaf(hj, w4.x, a4.x);
            a4.y = fmaf(hj, w4.y, a4.y);
            a4.z = fmaf(hj, w4.z, a4.z);
            a4.w = fmaf(hj, w4.w, a4.w);
        }
        a4.x = fmaxf(a4.x, 0.f); a4.y = fmaxf(a4.y, 0.f);
        a4.z = fmaxf(a4.z, 0.f); a4.w = fmaxf(a4.w, 0.f);
        *(float4*)&as_[w][lane * 4] = a4;
        __syncwarp();

        float f0 = b2s[2 * lane], f1 = b2s[2 * lane + 1];
        #pragma unroll 16
        for (int m = 0; m < 128; m++) {
            const float  am = as_[w][m];
            const float2 w2 = *(const float2*)&W2s[m * 64 + lane * 2];
            f0 = fmaf(am, w2.x, f0);
            f1 = fmaf(am, w2.y, f1);
        }

        float x0 = hs[w][2 * lane]     + f0;
        float x1 = hs[w][2 * lane + 1] + f1;

        float s = x0 + x1;
        #pragma unroll
        for (int o = 16; o > 0; o >>= 1) s += __shfl_xor_sync(0xffffffffu, s, o);
        const float mu = s * (1.0f / 64.0f);
        const float d0 = x0 - mu, d1 = x1 - mu;
        float sq = d0 * d0 + d1 * d1;
        #pragma unroll
        for (int o = 16; o > 0; o >>= 1) sq += __shfl_xor_sync(0xffffffffu, sq, o);
        const float rstd = rsqrtf(sq * (1.0f / 64.0f) + 1e-5f);

        const float y0 = d0 * rstd * gs[2 * lane]     + bs[2 * lane];
        const float y1 = d1 * rstd * gs[2 * lane + 1] + bs[2 * lane + 1];
        *(float2*)&g_h[tok * 64 + 2 * lane] = make_float2(y0, y1);

        float ss = y0 * y0 + y1 * y1;
        #pragma unroll
        for (int o = 16; o > 0; o >>= 1) ss += __shfl_xor_sync(0xffffffffu, ss, o);
        if (lane == 0) g_invd[tok] = 1.0f / (ss + 1e-6f);
        __syncwarp();
    }
}

// ---------------------------------------------------------------
// Phase 2: chunked delta-rule scan. One block (256 thr) per batch.
// Chunk C = 64. Per chunk:
//   U = M K^T       (parallel GEMM, M in registers)
//   G = K K^T       (lower-tri GEMM, overlapped with serial of prev chunk)
//   serial: dv_t = k_t - (U_t + sum_{s<t} G[t][s] dv_s) * invd_t
//   M += DV^T K     (parallel GEMM)
// ---------------------------------------------------------------

// shared layout (float offsets)
#define KS0  0        // K chunk buf0 [64][66]
#define KS1  4224     // K chunk buf1
#define GS0  8448     // Gram buf0 [64][64]  G[t][s] = k_s . k_t
#define GS1  12544    // Gram buf1
#define USF  16640    // U [64][64]  (U[t][e])
#define DVPO 20736    // packed dv history: per e: 33 ull (stride 33) -> 64*33 ull = 4224 floats
#define IV0  24960    // invd buf0 [64]
#define IV1  25024    // invd buf1 [64]
#define QSO  25088    // q [64]
#define CSO  25152    // ctx [64]
#define RSO  25216    // r  [64]
#define SMF  25280    // total floats

__device__ __forceinline__ void kload_chunk(float* sm, const float* __restrict__ hb,
                                            const float* __restrict__ idb,
                                            int chunk, int ksbase, int ivbase,
                                            int l, int n)
{
    const int cbase = chunk * 64;
    for (int q = l; q < 2048; q += n) {
        const int row = q >> 5, c2 = q & 31;
        const int tok = cbase + row;
        float2 v = make_float2(0.f, 0.f);
        if (tok <= 2046) v = *(const float2*)&hb[tok * 64 + c2 * 2];
        *(float2*)&sm[ksbase + row * 66 + c2 * 2] = v;
    }
    if (l < 64) {
        const int tok = cbase + l;
        sm[ivbase + l] = (tok <= 2046) ? idb[tok] : 0.f;
    }
}

// lower-triangular tile GEMM: G[t][s] for tile (ti,si), si<=ti (4x4 each)
__device__ __forceinline__ void gphase_tile(float* sm, int ksbase, int gsbase, int idx)
{
    if (idx >= 136) return;
    int ti = 0, rem = idx;
    while (rem >= ti + 1) { rem -= ti + 1; ti++; }
    const int si = rem;
    const int t0 = 4 * ti, s0 = 4 * si;

    ull acc[16];
    #pragma unroll
    for (int i = 0; i < 16; i++) acc[i] = 0ull;

    #pragma unroll 4
    for (int j2 = 0; j2 < 32; j2++) {
        ull kt[4], ks[4];
        #pragma unroll
        for (int a = 0; a < 4; a++)
            kt[a] = *(const ull*)&sm[ksbase + (t0 + a) * 66 + 2 * j2];
        #pragma unroll
        for (int b = 0; b < 4; b++)
            ks[b] = *(const ull*)&sm[ksbase + (s0 + b) * 66 + 2 * j2];
        #pragma unroll
        for (int a = 0; a < 4; a++)
            #pragma unroll
            for (int b = 0; b < 4; b++)
                acc[a * 4 + b] = ffma2(kt[a], ks[b], acc[a * 4 + b]);
    }
    #pragma unroll
    for (int a = 0; a < 4; a++)
        #pragma unroll
        for (int b = 0; b < 4; b++) {
            float lo, hi;
            funpack2(acc[a * 4 + b], lo, hi);
            sm[gsbase + (t0 + a) * 64 + s0 + b] = lo + hi;
        }
}

__global__ __launch_bounds__(256, 1) void scan_kernel(
    const float* __restrict__ Wr, const float* __restrict__ br,
    const float* __restrict__ Wo, const float* __restrict__ bo,
    float* __restrict__ out)
{
    extern __shared__ float sm[];
    const int b   = blockIdx.x;
    const int tid = threadIdx.x;
    const int w    = tid >> 5;
    const int lane = tid & 31;
    const int r    = lane >> 2;   // row within warp group (0..7)
    const int jq   = lane & 3;    // j-quarter (owns j in [16*jq, 16*jq+16))
    const int erow = 8 * w + r;   // M row owned by this thread (with 3 others)

    const float* hb  = g_h    + (size_t)b * LSEQ * HD;
    const float* idb = g_invd + (size_t)b * LSEQ;

    // M[erow][16*jq .. 16*jq+16) as 8 f32x2 registers
    ull Mr[8];
    #pragma unroll
    for (int i = 0; i < 8; i++) Mr[i] = 0ull;

    // prologue: load chunk 0 + q, compute G0
    kload_chunk(sm, hb, idb, 0, KS0, IV0, tid, 256);
    if (tid < 64) sm[QSO + tid] = hb[2047 * 64 + tid];
    __syncthreads();
    gphase_tile(sm, KS0, GS0, tid);
    __syncthreads();

    for (int c = 0; c < 32; c++) {
        const int cur    = c & 1;
        const int ksc    = cur ? KS1 : KS0;
        const int gsc    = cur ? GS1 : GS0;
        const int ivc    = cur ? IV1 : IV0;
        const int ksn    = cur ? KS0 : KS1;
        const int gsn    = cur ? GS0 : GS1;
        const int ivn    = cur ? IV0 : IV1;

        // ---- U-phase: U[t][erow] = sum_j M[erow][j] * k_t[j] (all warps) ----
        #pragma unroll 2
        for (int t = 0; t < 64; t++) {
            const ull* kp = (const ull*)&sm[ksc + t * 66 + jq * 16];
            ull a = 0ull, bb = 0ull;
            #pragma unroll
            for (int i = 0; i < 4; i++) {
                a  = ffma2(Mr[2 * i],     kp[2 * i],     a);
                bb = ffma2(Mr[2 * i + 1], kp[2 * i + 1], bb);
            }
            float lo, hi;
            funpack2(fadd2(a, bb), lo, hi);
            float ps = lo + hi;
            ps += __shfl_xor_sync(0xffffffffu, ps, 1);
            ps += __shfl_xor_sync(0xffffffffu, ps, 2);
            if (jq == 0) sm[USF + t * 64 + erow] = ps;
        }
        __syncthreads();

        // ---- serial (warps 0-1) overlapped with next-chunk load+G (warps 2-7) ----
        if (tid < 64) {
            const int e = tid;
            ull* DVpe = (ull*)&sm[DVPO] + e * 33;
            float dv_prev = 0.f;
            for (int t = 0; t < 64; t++) {
                float acc = sm[USF + t * 64 + e];
                const ull* Gp = (const ull*)&sm[gsc + t * 64];
                const int np = t >> 1;
                ull a0 = 0ull, a1 = 0ull;
                int p = 0;
                #pragma unroll 2
                for (; p + 4 <= np; p += 4) {
                    a0 = ffma2(Gp[p],     DVpe[p],     a0);
                    a1 = ffma2(Gp[p + 1], DVpe[p + 1], a1);
                    a0 = ffma2(Gp[p + 2], DVpe[p + 2], a0);
                    a1 = ffma2(Gp[p + 3], DVpe[p + 3], a1);
                }
                for (; p < np; ++p) a0 = ffma2(Gp[p], DVpe[p], a0);
                float lo, hi;
                funpack2(fadd2(a0, a1), lo, hi);
                float s = lo + hi;
                if (t & 1) s = fmaf(sm[gsc + t * 64 + (t - 1)], dv_prev, s);
                const float dv = sm[ksc + t * 66 + e] - (acc + s) * sm[ivc + t];
                if (t & 1) DVpe[t >> 1] = fpack2(dv_prev, dv);
                else       dv_prev = dv;
            }
        } else {
            if (c + 1 < 32) {
                kload_chunk(sm, hb, idb, c + 1, ksn, ivn, tid - 64, 192);
                asm volatile("bar.sync 1, 192;" ::: "memory");
                gphase_tile(sm, ksn, gsn, tid - 64);
            }
        }
        __syncthreads();

        // ---- M update: M[erow][j] += dv[t][erow] * k_t[j] (all warps) ----
        #pragma unroll 2
        for (int t = 0; t < 64; t++) {
            const ull d2 = *((const ull*)&sm[DVPO] + erow * 33 + (t >> 1));
            float dlo, dhi;
            funpack2(d2, dlo, dhi);
            const float dvs = (t & 1) ? dhi : dlo;
            const ull dv2 = fpack2(dvs, dvs);
            const ull* kp = (const ull*)&sm[ksc + t * 66 + jq * 16];
            #pragma unroll
            for (int i = 0; i < 8; i++) Mr[i] = ffma2(dv2, kp[i], Mr[i]);
        }
        // no barrier needed: next U-phase touches only Ks[next]/own regs/Us,
        // and DVs are next written only after the next post-U barrier.
    }

    // ---- ctx = M q ----
    {
        const ull* qp = (const ull*)&sm[QSO + jq * 16];
        ull a = 0ull, bb = 0ull;
        #pragma unroll
        for (int i = 0; i < 4; i++) {
            a  = ffma2(Mr[2 * i],     qp[2 * i],     a);
            bb = ffma2(Mr[2 * i + 1], qp[2 * i + 1], bb);
        }
        float lo, hi;
        funpack2(fadd2(a, bb), lo, hi);
        float ps = lo + hi;
        ps += __shfl_xor_sync(0xffffffffu, ps, 1);
        ps += __shfl_xor_sync(0xffffffffu, ps, 2);
        if (jq == 0) sm[CSO + erow] = ps;
    }
    __syncthreads();

    // ---- out = (ctx @ Wr + br) @ Wo + bo ----
    if (tid < 64) {
        float rr = br[tid];
        #pragma unroll 8
        for (int j = 0; j < 64; j++) rr = fmaf(sm[CSO + j], Wr[j * 64 + tid], rr);
        sm[RSO + tid] = rr;
    }
    __syncthreads();
    if (tid < 64) {
        float o = bo[tid];
        #pragma unroll 8
        for (int j = 0; j < 64; j++) o = fmaf(sm[RSO + j], Wo[j * 64 + tid], o);
        out[b * 64 + tid] = o;
    }
}

// ---------------------------------------------------------------
extern "C" void kernel_launch(void* const* d_in, const int* in_sizes, int n_in,
                              void* d_out, int out_size)
{
    const int*   seq   = (const int*)  d_in[0];
    const float* embed = (const float*)d_in[1];
    const float* W1    = (const float*)d_in[2];
    const float* b1    = (const float*)d_in[3];
    const float* W2    = (const float*)d_in[4];
    const float* b2    = (const float*)d_in[5];
    const float* gamma = (const float*)d_in[6];
    const float* beta  = (const float*)d_in[7];
    const float* Wr    = (const float*)d_in[8];
    const float* br    = (const float*)d_in[9];
    const float* Wo    = (const float*)d_in[10];
    const float* bo    = (const float*)d_in[11];
    float* out = (float*)d_out;

    (void)in_sizes; (void)n_in; (void)out_size;

    cudaFuncSetAttribute(phase1_kernel,
                         cudaFuncAttributeMaxDynamicSharedMemorySize, 65536);
    phase1_kernel<<<296, 256, 65536>>>(seq, embed, W1, b1, W2, b2, gamma, beta);

    cudaFuncSetAttribute(scan_kernel,
                         cudaFuncAttributeMaxDynamicSharedMemorySize, SMF * 4);
    scan_kernel<<<BATCH, 256, SMF * 4>>>(Wr, br, Wo, bo, out);
}

// round 7
// speedup vs baseline: 2.1027x; 2.1027x over previous
#include <cuda_runtime.h>

#define HD    64
#define LSEQ  2048
#define BATCH 16
#define NTOK  (BATCH * LSEQ)
#define NSTEP (LSEQ - 1)   // 2047 scan steps

typedef unsigned long long ull;

// Scratch (device globals: allocation-free)
__device__ float g_h[NTOK * HD];     // post-LN hidden states (8 MB)
__device__ float g_invd[NTOK];       // 1 / (||h||^2 + 1e-6) per token

// ---------------- packed f32x2 helpers (sm_103a) ----------------
__device__ __forceinline__ ull ffma2(ull a, ull b, ull c) {
    ull d;
    asm("fma.rn.f32x2 %0, %1, %2, %3;" : "=l"(d) : "l"(a), "l"(b), "l"(c));
    return d;
}
__device__ __forceinline__ ull fadd2(ull a, ull b) {
    ull d;
    asm("add.rn.f32x2 %0, %1, %2;" : "=l"(d) : "l"(a), "l"(b));
    return d;
}
__device__ __forceinline__ ull fpack2(float lo, float hi) {
    ull d;
    asm("mov.b64 %0, {%1, %2};" : "=l"(d) : "f"(lo), "f"(hi));
    return d;
}
__device__ __forceinline__ void funpack2(ull v, float& lo, float& hi) {
    asm("mov.b64 {%0, %1}, %2;" : "=f"(lo), "=f"(hi) : "l"(v));
}

// ---------------------------------------------------------------
// Phase 1: h = LN(embed[seq] + MLP(embed[seq])), plus inv_denom.
// One warp per token. W1/W2 live in dynamic shared (64 KB).
// (unchanged from round 1 — known good, ~50-60us)
// ---------------------------------------------------------------
__global__ __launch_bounds__(256) void phase1_kernel(
    const int*   __restrict__ seq,
    const float* __restrict__ embed,
    const float* __restrict__ W1,
    const float* __restrict__ b1,
    const float* __restrict__ W2,
    const float* __restrict__ b2,
    const float* __restrict__ gamma,
    const float* __restrict__ beta)
{
    extern __shared__ float dsm[];
    float* W1s = dsm;            // 64*128
    float* W2s = dsm + 64 * 128; // 128*64

    __shared__ __align__(16) float b1s[128];
    __shared__ float b2s[64], gs[64], bs[64];
    __shared__ __align__(16) float hs[8][64];
    __shared__ __align__(16) float as_[8][128];

    const int tid = threadIdx.x;
    for (int i = tid; i < 64 * 128; i += 256) W1s[i] = W1[i];
    for (int i = tid; i < 128 * 64; i += 256) W2s[i] = W2[i];
    if (tid < 128) b1s[tid] = b1[tid];
    if (tid < 64) { b2s[tid] = b2[tid]; gs[tid] = gamma[tid]; bs[tid] = beta[tid]; }
    __syncthreads();

    const int w    = tid >> 5;
    const int lane = tid & 31;
    const int gw   = blockIdx.x * 8 + w;
    const int nw   = gridDim.x * 8;

    for (int tok = gw; tok < NTOK; tok += nw) {
        const int v = seq[tok];
        const float h0 = embed[v * 64 + lane];
        const float h1 = embed[v * 64 + 32 + lane];
        hs[w][lane]      = h0;
        hs[w][lane + 32] = h1;
        __syncwarp();

        float4 a4 = *(const float4*)&b1s[lane * 4];
        #pragma unroll 16
        for (int j = 0; j < 64; j++) {
            const float  hj = hs[w][j];
            const float4 w4 = *(const float4*)&W1s[j * 128 + lane * 4];
            a4.x = fmaf(hj, w4.x, a4.x);
            a4.y = fmaf(hj, w4.y, a4.y);
            a4.z = fmaf(hj, w4.z, a4.z);
            a4.w = fmaf(hj, w4.w, a4.w);
        }
        a4.x = fmaxf(a4.x, 0.f); a4.y = fmaxf(a4.y, 0.f);
        a4.z = fmaxf(a4.z, 0.f); a4.w = fmaxf(a4.w, 0.f);
        *(float4*)&as_[w][lane * 4] = a4;
        __syncwarp();

        float f0 = b2s[2 * lane], f1 = b2s[2 * lane + 1];
        #pragma unroll 16
        for (int m = 0; m < 128; m++) {
            const float  am = as_[w][m];
            const float2 w2 = *(const float2*)&W2s[m * 64 + lane * 2];
            f0 = fmaf(am, w2.x, f0);
            f1 = fmaf(am, w2.y, f1);
        }

        float x0 = hs[w][2 * lane]     + f0;
        float x1 = hs[w][2 * lane + 1] + f1;

        float s = x0 + x1;
        #pragma unroll
        for (int o = 16; o > 0; o >>= 1) s += __shfl_xor_sync(0xffffffffu, s, o);
        const float mu = s * (1.0f / 64.0f);
        const float d0 = x0 - mu, d1 = x1 - mu;
        float sq = d0 * d0 + d1 * d1;
        #pragma unroll
        for (int o = 16; o > 0; o >>= 1) sq += __shfl_xor_sync(0xffffffffu, sq, o);
        const float rstd = rsqrtf(sq * (1.0f / 64.0f) + 1e-5f);

        const float y0 = d0 * rstd * gs[2 * lane]     + bs[2 * lane];
        const float y1 = d1 * rstd * gs[2 * lane + 1] + bs[2 * lane + 1];
        *(float2*)&g_h[tok * 64 + 2 * lane] = make_float2(y0, y1);

        float ss = y0 * y0 + y1 * y1;
        #pragma unroll
        for (int o = 16; o > 0; o >>= 1) ss += __shfl_xor_sync(0xffffffffu, ss, o);
        if (lane == 0) g_invd[tok] = 1.0f / (ss + 1e-6f);
        __syncwarp();
    }
}

// ---------------------------------------------------------------
// Phase 2: barrier-free register-resident delta-rule scan.
// 16 blocks x 128 threads. Thread pair (2e, 2e+1) owns M row e:
// thread q owns cols [32q, 32q+32) as 16 f32x2 registers.
// Per step t:
//   dv    = k_t[e] - pre * invd_t        (pre = M_t . k_t, from last iter)
//   M    += dv * k_t  (own slice)
//   pre   = M . k_{t+1}  (slice dot + shfl.xor(1) pair-reduce)
// k slices double-buffered in registers, distance-2 global prefetch.
// No shared memory, no barriers in the main loop.
// ---------------------------------------------------------------

__device__ __forceinline__ void load_slice(ull* d, const float* __restrict__ p) {
    #pragma unroll
    for (int i = 0; i < 8; i++) {
        const float4 v = *(const float4*)(p + 4 * i);
        d[2 * i]     = fpack2(v.x, v.y);
        d[2 * i + 1] = fpack2(v.z, v.w);
    }
}

__device__ __forceinline__ float dotred(const ull* M, const ull* k) {
    ull a0 = 0ull, a1 = 0ull, a2 = 0ull, a3 = 0ull;
    #pragma unroll
    for (int i = 0; i < 16; i += 4) {
        a0 = ffma2(M[i],     k[i],     a0);
        a1 = ffma2(M[i + 1], k[i + 1], a1);
        a2 = ffma2(M[i + 2], k[i + 2], a2);
        a3 = ffma2(M[i + 3], k[i + 3], a3);
    }
    const ull s = fadd2(fadd2(a0, a1), fadd2(a2, a3));
    float lo, hi;
    funpack2(s, lo, hi);
    float p = lo + hi;
    p += __shfl_xor_sync(0xffffffffu, p, 1);
    return p;
}

__global__ __launch_bounds__(128, 1) void scan_kernel(
    const float* __restrict__ Wr, const float* __restrict__ br,
    const float* __restrict__ Wo, const float* __restrict__ bo,
    float* __restrict__ out)
{
    const int b   = blockIdx.x;
    const int tid = threadIdx.x;
    const int e   = tid >> 1;    // row 0..63
    const int q   = tid & 1;     // column half

    const float* __restrict__ hb  = g_h    + (size_t)b * LSEQ * HD;
    const float* __restrict__ idb = g_invd + (size_t)b * LSEQ;
    const float* __restrict__ kp  = hb + q * 32;   // this thread's slice base

    __shared__ float cs[64], rs[64];

    ull M[16];
    #pragma unroll
    for (int i = 0; i < 16; i++) M[i] = 0ull;

    ull ka[16], kbf[16];
    load_slice(ka,  kp);          // token 0
    load_slice(kbf, kp + 64);     // token 1
    float sa = hb[e];             // k_0[e]
    float sb = hb[64 + e];        // k_1[e]
    float ia = idb[0];
    float ib = idb[1];
    float pre = 0.0f;             // M_0 . k_0 = 0

    #pragma unroll 1
    for (int t = 0; t < NSTEP - 1; t += 2) {
        // ---- step t (even): cur = ka, next = kbf ----
        {
            const float dv  = fmaf(-pre, ia, sa);
            const ull   dv2 = fpack2(dv, dv);
            #pragma unroll
            for (int i = 0; i < 16; i++) M[i] = ffma2(dv2, ka[i], M[i]);
            // prefetch token t+2 into ka (regs just freed)
            load_slice(ka, kp + (t + 2) * 64);
            sa = hb[(t + 2) * 64 + e];
            ia = idb[t + 2];
            pre = dotred(M, kbf);                 // M_{t+1} . k_{t+1}
        }
        // ---- step t+1 (odd): cur = kbf, next = ka ----
        {
            const float dv  = fmaf(-pre, ib, sb);
            const ull   dv2 = fpack2(dv, dv);
            #pragma unroll
            for (int i = 0; i < 16; i++) M[i] = ffma2(dv2, kbf[i], M[i]);
            // prefetch token t+3 into kbf
            load_slice(kbf, kp + (t + 3) * 64);
            sb = hb[(t + 3) * 64 + e];
            ib = idb[t + 3];
            pre = dotred(M, ka);                  // M_{t+2} . k_{t+2}
        }
    }
    // final step t = NSTEP-1 = 2046: cur = ka (token 2046), next = kbf (token 2047 = q)
    {
        const float dv  = fmaf(-pre, ia, sa);
        const ull   dv2 = fpack2(dv, dv);
        #pragma unroll
        for (int i = 0; i < 16; i++) M[i] = ffma2(dv2, ka[i], M[i]);
    }
    // ctx = M_final . q  (kbf holds token 2047)
    const float ctx = dotred(M, kbf);
    if (q == 0) cs[e] = ctx;
    __syncthreads();

    // out = (ctx @ Wr + br) @ Wo + bo
    if (tid < 64) {
        float rr = br[tid];
        #pragma unroll 8
        for (int j = 0; j < 64; j++) rr = fmaf(cs[j], Wr[j * 64 + tid], rr);
        rs[tid] = rr;
    }
    __syncthreads();
    if (tid < 64) {
        float o = bo[tid];
        #pragma unroll 8
        for (int j = 0; j < 64; j++) o = fmaf(rs[j], Wo[j * 64 + tid], o);
        out[b * 64 + tid] = o;
    }
}

// ---------------------------------------------------------------
extern "C" void kernel_launch(void* const* d_in, const int* in_sizes, int n_in,
                              void* d_out, int out_size)
{
    const int*   seq   = (const int*)  d_in[0];
    const float* embed = (const float*)d_in[1];
    const float* W1    = (const float*)d_in[2];
    const float* b1    = (const float*)d_in[3];
    const float* W2    = (const float*)d_in[4];
    const float* b2    = (const float*)d_in[5];
    const float* gamma = (const float*)d_in[6];
    const float* beta  = (const float*)d_in[7];
    const float* Wr    = (const float*)d_in[8];
    const float* br    = (const float*)d_in[9];
    const float* Wo    = (const float*)d_in[10];
    const float* bo    = (const float*)d_in[11];
    float* out = (float*)d_out;

    (void)in_sizes; (void)n_in; (void)out_size;

    cudaFuncSetAttribute(phase1_kernel,
                         cudaFuncAttributeMaxDynamicSharedMemorySize, 65536);
    phase1_kernel<<<296, 256, 65536>>>(seq, embed, W1, b1, W2, b2, gamma, beta);

    scan_kernel<<<BATCH, 128>>>(Wr, br, Wo, bo, out);
}

// round 8
// speedup vs baseline: 3.6633x; 1.7422x over previous
#include <cuda_runtime.h>

#define HD    64
#define LSEQ  2048
#define BATCH 16
#define NTOK  (BATCH * LSEQ)
#define NSTEP (LSEQ - 1)   // 2047 scan steps
#define RING  32

typedef unsigned long long ull;

// Scratch (device globals, zero-initialized; pad regions never written -> stay 0)
__device__ float g_h[(NTOK + 16) * HD];   // post-LN hidden states (+pad)
__device__ float g_invd[NTOK + 16];       // 1 / (||h||^2 + 1e-6)
__device__ float g_gram[(NTOK + 16) * 4]; // g_j[t] = k_{t-j} . k_t, j=1..4
__device__ float g_ctx[BATCH * HD];       // ctx = M_final . q

// ---------------- packed f32x2 helpers (sm_103a) ----------------
__device__ __forceinline__ ull ffma2(ull a, ull b, ull c) {
    ull d;
    asm("fma.rn.f32x2 %0, %1, %2, %3;" : "=l"(d) : "l"(a), "l"(b), "l"(c));
    return d;
}
__device__ __forceinline__ ull fadd2(ull a, ull b) {
    ull d;
    asm("add.rn.f32x2 %0, %1, %2;" : "=l"(d) : "l"(a), "l"(b));
    return d;
}
__device__ __forceinline__ ull fpack2(float lo, float hi) {
    ull d;
    asm("mov.b64 %0, {%1, %2};" : "=l"(d) : "f"(lo), "f"(hi));
    return d;
}
__device__ __forceinline__ void funpack2(ull v, float& lo, float& hi) {
    asm("mov.b64 {%0, %1}, %2;" : "=f"(lo), "=f"(hi) : "l"(v));
}

// ---------------------------------------------------------------
// Phase 1: h = LN(embed[seq] + MLP(embed[seq])), plus inv_denom.
// (unchanged — known good)
// ---------------------------------------------------------------
__global__ __launch_bounds__(256) void phase1_kernel(
    const int*   __restrict__ seq,
    const float* __restrict__ embed,
    const float* __restrict__ W1,
    const float* __restrict__ b1,
    const float* __restrict__ W2,
    const float* __restrict__ b2,
    const float* __restrict__ gamma,
    const float* __restrict__ beta)
{
    extern __shared__ float dsm[];
    float* W1s = dsm;            // 64*128
    float* W2s = dsm + 64 * 128; // 128*64

    __shared__ __align__(16) float b1s[128];
    __shared__ float b2s[64], gs[64], bs[64];
    __shared__ __align__(16) float hs[8][64];
    __shared__ __align__(16) float as_[8][128];

    const int tid = threadIdx.x;
    for (int i = tid; i < 64 * 128; i += 256) W1s[i] = W1[i];
    for (int i = tid; i < 128 * 64; i += 256) W2s[i] = W2[i];
    if (tid < 128) b1s[tid] = b1[tid];
    if (tid < 64) { b2s[tid] = b2[tid]; gs[tid] = gamma[tid]; bs[tid] = beta[tid]; }
    __syncthreads();

    const int w    = tid >> 5;
    const int lane = tid & 31;
    const int gw   = blockIdx.x * 8 + w;
    const int nw   = gridDim.x * 8;

    for (int tok = gw; tok < NTOK; tok += nw) {
        const int v = seq[tok];
        const float h0 = embed[v * 64 + lane];
        const float h1 = embed[v * 64 + 32 + lane];
        hs[w][lane]      = h0;
        hs[w][lane + 32] = h1;
        __syncwarp();

        float4 a4 = *(const float4*)&b1s[lane * 4];
        #pragma unroll 16
        for (int j = 0; j < 64; j++) {
            const float  hj = hs[w][j];
            const float4 w4 = *(const float4*)&W1s[j * 128 + lane * 4];
            a4.x = fmaf(hj, w4.x, a4.x);
            a4.y = fmaf(hj, w4.y, a4.y);
            a4.z = fmaf(hj, w4.z, a4.z);
            a4.w = fmaf(hj, w4.w, a4.w);
        }
        a4.x = fmaxf(a4.x, 0.f); a4.y = fmaxf(a4.y, 0.f);
        a4.z = fmaxf(a4.z, 0.f); a4.w = fmaxf(a4.w, 0.f);
        *(float4*)&as_[w][lane * 4] = a4;
        __syncwarp();

        float f0 = b2s[2 * lane], f1 = b2s[2 * lane + 1];
        #pragma unroll 16
        for (int m = 0; m < 128; m++) {
            const float  am = as_[w][m];
            const float2 w2 = *(const float2*)&W2s[m * 64 + lane * 2];
            f0 = fmaf(am, w2.x, f0);
            f1 = fmaf(am, w2.y, f1);
        }

        float x0 = hs[w][2 * lane]     + f0;
        float x1 = hs[w][2 * lane + 1] + f1;

        float s = x0 + x1;
        #pragma unroll
        for (int o = 16; o > 0; o >>= 1) s += __shfl_xor_sync(0xffffffffu, s, o);
        const float mu = s * (1.0f / 64.0f);
        const float d0 = x0 - mu, d1 = x1 - mu;
        float sq = d0 * d0 + d1 * d1;
        #pragma unroll
        for (int o = 16; o > 0; o >>= 1) sq += __shfl_xor_sync(0xffffffffu, sq, o);
        const float rstd = rsqrtf(sq * (1.0f / 64.0f) + 1e-5f);

        const float y0 = d0 * rstd * gs[2 * lane]     + bs[2 * lane];
        const float y1 = d1 * rstd * gs[2 * lane + 1] + bs[2 * lane + 1];
        *(float2*)&g_h[tok * 64 + 2 * lane] = make_float2(y0, y1);

        float ss = y0 * y0 + y1 * y1;
        #pragma unroll
        for (int o = 16; o > 0; o >>= 1) ss += __shfl_xor_sync(0xffffffffu, ss, o);
        if (lane == 0) g_invd[tok] = 1.0f / (ss + 1e-6f);
        __syncwarp();
    }
}

// ---------------------------------------------------------------
// Phase 1.5: Gram lookahead terms g_j[t] = k_{t-j} . k_t (j=1..4),
// masked to stay within each batch's sequence. Warp per token.
// ---------------------------------------------------------------
__global__ __launch_bounds__(256) void gram_kernel()
{
    const int wid  = (blockIdx.x * 256 + threadIdx.x) >> 5;
    const int lane = threadIdx.x & 31;
    if (wid >= NTOK) return;
    const int t   = wid;
    const int pos = t & (LSEQ - 1);

    const ull kt = *(const ull*)&g_h[t * 64 + 2 * lane];
    float res[4];
    #pragma unroll
    for (int j = 1; j <= 4; j++) {
        ull kj = 0ull;
        if (pos >= j) kj = *(const ull*)&g_h[(t - j) * 64 + 2 * lane];
        const ull a = ffma2(kt, kj, 0ull);
        float lo, hi;
        funpack2(a, lo, hi);
        float s = lo + hi;
        #pragma unroll
        for (int o = 16; o > 0; o >>= 1) s += __shfl_xor_sync(0xffffffffu, s, o);
        res[j - 1] = s;
    }
    if (lane == 0)
        *(float4*)&g_gram[t * 4] = make_float4(res[0], res[1], res[2], res[3]);
}

// ---------------------------------------------------------------
// Phase 2: row-independent delta-rule scan with depth-4 Gram lookahead.
// Grid 128 = 16 batches x 8 row-groups; 1 warp/block.
// Lane = r*4+q: row e = rg*8+r, col quarter q (16 cols = 8 f32x2 regs of M).
// Per step s:
//   pre_s = c_s + sum_{j=1..4} dv_{s-j} * g_j[s]      (c_s computed 5 steps ago)
//   dv_s  = k_s[e] - pre_s * invd_s                    (serial chain: 2 FMAs)
//   M    += dv_s * k_s
//   c_{s+5} = M . k_{s+5}  (dot + 2 shfls; 5 steps of slack)
// k/aux stream via 32-deep shared ring, produced 16 tokens ahead,
// one __syncwarp per 8-step unrolled iteration.
// ---------------------------------------------------------------
__global__ __launch_bounds__(32, 1) void scan_kernel()
{
    __shared__ __align__(16) float smk[RING][64];
    __shared__ __align__(16) float smaux[RING][8];  // g1..g4, invd

    const int bb   = blockIdx.x >> 3;
    const int rg   = blockIdx.x & 7;
    const int lane = threadIdx.x;
    const int r    = lane >> 2;
    const int q    = lane & 3;
    const int e    = rg * 8 + r;

    const float* __restrict__ hb  = g_h    + (size_t)bb * LSEQ * HD;
    const float* __restrict__ gga = g_gram + (size_t)bb * LSEQ * 4;
    const float* __restrict__ idb = g_invd + (size_t)bb * LSEQ;

    ull M[8];
    #pragma unroll
    for (int i = 0; i < 8; i++) M[i] = 0ull;
    float cr[8];
    #pragma unroll
    for (int i = 0; i < 8; i++) cr[i] = 0.0f;
    float dv1 = 0.f, dv2 = 0.f, dv3 = 0.f, dv4 = 0.f;

    // prologue: fill ring with tokens 0..15 (+aux)
    #pragma unroll
    for (int w = 0; w < 16; w++)
        *(float2*)&smk[w][2 * lane] = *(const float2*)&hb[w * 64 + 2 * lane];
    if (lane < 16) {
        *(float4*)&smaux[lane][0] = *(const float4*)&gga[lane * 4];
        smaux[lane][4] = idb[lane];
    }
    __syncwarp();

    // one scan step; u = S mod 8 (compile-time under unroll -> cr[] stays in regs)
    auto step = [&](int S, int u) {
        const int sl = S & (RING - 1);
        const int dl = (S + 5) & (RING - 1);
        const float  ke = smk[sl][e];
        const float4 gg = *(const float4*)&smaux[sl][0];
        const float  iv = smaux[sl][4];
        float partial = fmaf(dv2, gg.y, cr[u]);
        partial = fmaf(dv3, gg.z, partial);
        partial = fmaf(dv4, gg.w, partial);
        const float pre = fmaf(dv1, gg.x, partial);
        const float dv  = fmaf(-pre, iv, ke);
        const ull dvp = fpack2(dv, dv);
        const ull* kq = (const ull*)&smk[sl][q * 16];
        #pragma unroll
        for (int i = 0; i < 8; i++) M[i] = ffma2(dvp, kq[i], M[i]);
        const ull* kd = (const ull*)&smk[dl][q * 16];
        ull a0 = 0ull, a1 = 0ull;
        #pragma unroll
        for (int i = 0; i < 8; i += 2) {
            a0 = ffma2(M[i],     kd[i],     a0);
            a1 = ffma2(M[i + 1], kd[i + 1], a1);
        }
        float lo, hi;
        funpack2(fadd2(a0, a1), lo, hi);
        float c = lo + hi;
        c += __shfl_xor_sync(0xffffffffu, c, 1);
        c += __shfl_xor_sync(0xffffffffu, c, 2);
        cr[(u + 5) & 7] = c;
        dv4 = dv3; dv3 = dv2; dv2 = dv1; dv1 = dv;
    };

    #pragma unroll 1
    for (int tb = 0; tb < 2040; tb += 8) {
        // produce tokens tb+16 .. tb+23 (consumed next iterations; pad-safe)
        #pragma unroll
        for (int w = 0; w < 8; w++) {
            const int tok = tb + 16 + w;
            const int ps  = tok & (RING - 1);
            *(float2*)&smk[ps][2 * lane] = *(const float2*)&hb[tok * 64 + 2 * lane];
        }
        if (lane < 8) {
            const int tok = tb + 16 + lane;
            const int ps  = tok & (RING - 1);
            *(float4*)&smaux[ps][0] = *(const float4*)&gga[tok * 4];
            smaux[ps][4] = idb[tok];
        }
        #pragma unroll
        for (int u = 0; u < 8; u++) step(tb + u, u);
        __syncwarp();
    }
    // tail steps 2040..2046 (ring already holds tokens through 2055)
    #pragma unroll
    for (int u = 0; u < 7; u++) step(2040 + u, u);

    // ctx = M_final . k_2047  (token 2047 lives at slot 2047 & 31 = 31)
    {
        const ull* kq = (const ull*)&smk[2047 & (RING - 1)][q * 16];
        ull a0 = 0ull, a1 = 0ull;
        #pragma unroll
        for (int i = 0; i < 8; i += 2) {
            a0 = ffma2(M[i],     kq[i],     a0);
            a1 = ffma2(M[i + 1], kq[i + 1], a1);
        }
        float lo, hi;
        funpack2(fadd2(a0, a1), lo, hi);
        float c = lo + hi;
        c += __shfl_xor_sync(0xffffffffu, c, 1);
        c += __shfl_xor_sync(0xffffffffu, c, 2);
        if (q == 0) g_ctx[bb * 64 + e] = c;
    }
}

// ---------------------------------------------------------------
// Phase 3: out = (ctx @ Wr + br) @ Wo + bo
// ---------------------------------------------------------------
__global__ __launch_bounds__(64) void proj_kernel(
    const float* __restrict__ Wr, const float* __restrict__ br,
    const float* __restrict__ Wo, const float* __restrict__ bo,
    float* __restrict__ out)
{
    __shared__ float cs[64], rs[64];
    const int b   = blockIdx.x;
    const int tid = threadIdx.x;
    cs[tid] = g_ctx[b * 64 + tid];
    __syncthreads();
    float rr = br[tid];
    #pragma unroll 8
    for (int j = 0; j < 64; j++) rr = fmaf(cs[j], Wr[j * 64 + tid], rr);
    rs[tid] = rr;
    __syncthreads();
    float o = bo[tid];
    #pragma unroll 8
    for (int j = 0; j < 64; j++) o = fmaf(rs[j], Wo[j * 64 + tid], o);
    out[b * 64 + tid] = o;
}

// ---------------------------------------------------------------
extern "C" void kernel_launch(void* const* d_in, const int* in_sizes, int n_in,
                              void* d_out, int out_size)
{
    const int*   seq   = (const int*)  d_in[0];
    const float* embed = (const float*)d_in[1];
    const float* W1    = (const float*)d_in[2];
    const float* b1    = (const float*)d_in[3];
    const float* W2    = (const float*)d_in[4];
    const float* b2    = (const float*)d_in[5];
    const float* gamma = (const float*)d_in[6];
    const float* beta  = (const float*)d_in[7];
    const float* Wr    = (const float*)d_in[8];
    const float* br    = (const float*)d_in[9];
    const float* Wo    = (const float*)d_in[10];
    const float* bo    = (const float*)d_in[11];
    float* out = (float*)d_out;

    (void)in_sizes; (void)n_in; (void)out_size;

    cudaFuncSetAttribute(phase1_kernel,
                         cudaFuncAttributeMaxDynamicSharedMemorySize, 65536);
    phase1_kernel<<<296, 256, 65536>>>(seq, embed, W1, b1, W2, b2, gamma, beta);
    gram_kernel<<<NTOK / 8, 256>>>();
    scan_kernel<<<BATCH * 8, 32>>>();
    proj_kernel<<<BATCH, 64>>>(Wr, br, Wo, bo, out);
}

// round 9
// speedup vs baseline: 4.2544x; 1.1614x over previous
#include <cuda_runtime.h>

#define HD    64
#define LSEQ  2048
#define BATCH 16
#define NTOK  (BATCH * LSEQ)
#define NSTEP (LSEQ - 1)   // 2047 scan steps
#define RING  32

typedef unsigned long long ull;

// Scratch (device globals, zero-initialized; pad regions never written -> stay 0)
__device__ float g_h[(NTOK + 16) * HD];   // post-LN hidden states (+pad)
__device__ float g_invd[NTOK + 16];       // 1 / (||h||^2 + 1e-6)
__device__ float g_gram[(NTOK + 16) * 4]; // g_j[t] = k_{t-j} . k_t, j=1..4
__device__ float g_ctx[BATCH * HD];       // ctx = M_final . q

// ---------------- packed f32x2 helpers (sm_103a) ----------------
__device__ __forceinline__ ull ffma2(ull a, ull b, ull c) {
    ull d;
    asm("fma.rn.f32x2 %0, %1, %2, %3;" : "=l"(d) : "l"(a), "l"(b), "l"(c));
    return d;
}
__device__ __forceinline__ ull fadd2(ull a, ull b) {
    ull d;
    asm("add.rn.f32x2 %0, %1, %2;" : "=l"(d) : "l"(a), "l"(b));
    return d;
}
__device__ __forceinline__ ull fpack2(float lo, float hi) {
    ull d;
    asm("mov.b64 %0, {%1, %2};" : "=l"(d) : "f"(lo), "f"(hi));
    return d;
}
__device__ __forceinline__ void funpack2(ull v, float& lo, float& hi) {
    asm("mov.b64 {%0, %1}, %2;" : "=f"(lo), "=f"(hi) : "l"(v));
}

// ---------------------------------------------------------------
// Phase 1: h = LN(embed[seq] + MLP(embed[seq])), plus inv_denom.
// (unchanged — known good)
// ---------------------------------------------------------------
__global__ __launch_bounds__(256) void phase1_kernel(
    const int*   __restrict__ seq,
    const float* __restrict__ embed,
    const float* __restrict__ W1,
    const float* __restrict__ b1,
    const float* __restrict__ W2,
    const float* __restrict__ b2,
    const float* __restrict__ gamma,
    const float* __restrict__ beta)
{
    extern __shared__ float dsm[];
    float* W1s = dsm;            // 64*128
    float* W2s = dsm + 64 * 128; // 128*64

    __shared__ __align__(16) float b1s[128];
    __shared__ float b2s[64], gs[64], bs[64];
    __shared__ __align__(16) float hs[8][64];
    __shared__ __align__(16) float as_[8][128];

    const int tid = threadIdx.x;
    for (int i = tid; i < 64 * 128; i += 256) W1s[i] = W1[i];
    for (int i = tid; i < 128 * 64; i += 256) W2s[i] = W2[i];
    if (tid < 128) b1s[tid] = b1[tid];
    if (tid < 64) { b2s[tid] = b2[tid]; gs[tid] = gamma[tid]; bs[tid] = beta[tid]; }
    __syncthreads();

    const int w    = tid >> 5;
    const int lane = tid & 31;
    const int gw   = blockIdx.x * 8 + w;
    const int nw   = gridDim.x * 8;

    for (int tok = gw; tok < NTOK; tok += nw) {
        const int v = seq[tok];
        const float h0 = embed[v * 64 + lane];
        const float h1 = embed[v * 64 + 32 + lane];
        hs[w][lane]      = h0;
        hs[w][lane + 32] = h1;
        __syncwarp();

        float4 a4 = *(const float4*)&b1s[lane * 4];
        #pragma unroll 16
        for (int j = 0; j < 64; j++) {
            const float  hj = hs[w][j];
            const float4 w4 = *(const float4*)&W1s[j * 128 + lane * 4];
            a4.x = fmaf(hj, w4.x, a4.x);
            a4.y = fmaf(hj, w4.y, a4.y);
            a4.z = fmaf(hj, w4.z, a4.z);
            a4.w = fmaf(hj, w4.w, a4.w);
        }
        a4.x = fmaxf(a4.x, 0.f); a4.y = fmaxf(a4.y, 0.f);
        a4.z = fmaxf(a4.z, 0.f); a4.w = fmaxf(a4.w, 0.f);
        *(float4*)&as_[w][lane * 4] = a4;
        __syncwarp();

        float f0 = b2s[2 * lane], f1 = b2s[2 * lane + 1];
        #pragma unroll 16
        for (int m = 0; m < 128; m++) {
            const float  am = as_[w][m];
            const float2 w2 = *(const float2*)&W2s[m * 64 + lane * 2];
            f0 = fmaf(am, w2.x, f0);
            f1 = fmaf(am, w2.y, f1);
        }

        float x0 = hs[w][2 * lane]     + f0;
        float x1 = hs[w][2 * lane + 1] + f1;

        float s = x0 + x1;
        #pragma unroll
        for (int o = 16; o > 0; o >>= 1) s += __shfl_xor_sync(0xffffffffu, s, o);
        const float mu = s * (1.0f / 64.0f);
        const float d0 = x0 - mu, d1 = x1 - mu;
        float sq = d0 * d0 + d1 * d1;
        #pragma unroll
        for (int o = 16; o > 0; o >>= 1) sq += __shfl_xor_sync(0xffffffffu, sq, o);
        const float rstd = rsqrtf(sq * (1.0f / 64.0f) + 1e-5f);

        const float y0 = d0 * rstd * gs[2 * lane]     + bs[2 * lane];
        const float y1 = d1 * rstd * gs[2 * lane + 1] + bs[2 * lane + 1];
        *(float2*)&g_h[tok * 64 + 2 * lane] = make_float2(y0, y1);

        float ss = y0 * y0 + y1 * y1;
        #pragma unroll
        for (int o = 16; o > 0; o >>= 1) ss += __shfl_xor_sync(0xffffffffu, ss, o);
        if (lane == 0) g_invd[tok] = 1.0f / (ss + 1e-6f);
        __syncwarp();
    }
}

// ---------------------------------------------------------------
// Phase 1.5: Gram lookahead terms g_j[t] = k_{t-j} . k_t (j=1..4),
// masked to stay within each batch's sequence. Warp per token.
// ---------------------------------------------------------------
__global__ __launch_bounds__(256) void gram_kernel()
{
    const int wid  = (blockIdx.x * 256 + threadIdx.x) >> 5;
    const int lane = threadIdx.x & 31;
    if (wid >= NTOK) return;
    const int t   = wid;
    const int pos = t & (LSEQ - 1);

    const ull kt = *(const ull*)&g_h[t * 64 + 2 * lane];
    float res[4];
    #pragma unroll
    for (int j = 1; j <= 4; j++) {
        ull kj = 0ull;
        if (pos >= j) kj = *(const ull*)&g_h[(t - j) * 64 + 2 * lane];
        const ull a = ffma2(kt, kj, 0ull);
        float lo, hi;
        funpack2(a, lo, hi);
        float s = lo + hi;
        #pragma unroll
        for (int o = 16; o > 0; o >>= 1) s += __shfl_xor_sync(0xffffffffu, s, o);
        res[j - 1] = s;
    }
    if (lane == 0)
        *(float4*)&g_gram[t * 4] = make_float4(res[0], res[1], res[2], res[3]);
}

// ---------------------------------------------------------------
// Phase 2: row-independent delta-rule scan, depth-4 Gram lookahead,
// columns split 8 ways across 2 warps (64 threads/block).
// Grid 128 = 16 batches x 8 row-groups.
// Thread (r, c8): row e = rg*8+r, cols [8*c8, 8*c8+8) as 4 f32x2 regs.
// Per step s:
//   pre_s = c_s + sum_{j=1..4} dv_{s-j} * g_j[s]   (c_s computed 5 steps ago)
//   dv_s  = k_s[e] - pre_s * invd_s                 (serial chain: 2 FMAs)
//   M    += dv_s * k_s                              (4 ffma2)
//   c_{s+5} = M . k_{s+5}                           (4 ffma2 + 3 shfl, 5-step slack)
// k/aux via 32-deep shared ring, produced 16 ahead, __syncthreads per 8 steps.
// ---------------------------------------------------------------
__global__ __launch_bounds__(64, 1) void scan_kernel()
{
    __shared__ __align__(16) float smk[RING][64];
    __shared__ __align__(16) float smaux[RING][8];  // g1..g4, invd

    const int bb   = blockIdx.x >> 3;
    const int rg   = blockIdx.x & 7;
    const int tid  = threadIdx.x;
    const int lane = tid & 31;
    const int r    = tid >> 3;     // row within group 0..7
    const int c8   = tid & 7;      // column eighth
    const int e    = rg * 8 + r;

    const float* __restrict__ hb  = g_h    + (size_t)bb * LSEQ * HD;
    const float* __restrict__ gga = g_gram + (size_t)bb * LSEQ * 4;
    const float* __restrict__ idb = g_invd + (size_t)bb * LSEQ;

    ull M[4];
    #pragma unroll
    for (int i = 0; i < 4; i++) M[i] = 0ull;
    float cr[8];
    #pragma unroll
    for (int i = 0; i < 8; i++) cr[i] = 0.0f;
    float dv1 = 0.f, dv2 = 0.f, dv3 = 0.f, dv4 = 0.f;

    // prologue: fill ring with tokens 0..15 (+aux). Warp w loads odd/even tokens.
    #pragma unroll
    for (int w = 0; w < 8; w++) {
        const int tok = 2 * w + (tid >> 5);
        *(float2*)&smk[tok][2 * lane] = *(const float2*)&hb[tok * 64 + 2 * lane];
    }
    if (tid < 16) {
        *(float4*)&smaux[tid][0] = *(const float4*)&gga[tid * 4];
        smaux[tid][4] = idb[tid];
    }
    __syncthreads();

    // one scan step; u = S mod 8 (compile-time under unroll -> cr[] stays in regs)
    auto step = [&](int S, int u) {
        const int sl = S & (RING - 1);
        const int dl = (S + 5) & (RING - 1);
        const float  ke = smk[sl][e];
        const float4 gg = *(const float4*)&smaux[sl][0];
        const float  iv = smaux[sl][4];
        float partial = fmaf(dv2, gg.y, cr[u]);
        partial = fmaf(dv3, gg.z, partial);
        partial = fmaf(dv4, gg.w, partial);
        const float pre = fmaf(dv1, gg.x, partial);
        const float dv  = fmaf(-pre, iv, ke);
        const ull dvp = fpack2(dv, dv);
        const ull* kq = (const ull*)&smk[sl][c8 * 8];
        #pragma unroll
        for (int i = 0; i < 4; i++) M[i] = ffma2(dvp, kq[i], M[i]);
        const ull* kd = (const ull*)&smk[dl][c8 * 8];
        ull a0 = ffma2(M[0], kd[0], 0ull);
        ull a1 = ffma2(M[1], kd[1], 0ull);
        a0 = ffma2(M[2], kd[2], a0);
        a1 = ffma2(M[3], kd[3], a1);
        float lo, hi;
        funpack2(fadd2(a0, a1), lo, hi);
        float c = lo + hi;
        c += __shfl_xor_sync(0xffffffffu, c, 1);
        c += __shfl_xor_sync(0xffffffffu, c, 2);
        c += __shfl_xor_sync(0xffffffffu, c, 4);
        cr[(u + 5) & 7] = c;
        dv4 = dv3; dv3 = dv2; dv2 = dv1; dv1 = dv;
    };

    #pragma unroll 1
    for (int tb = 0; tb < 2040; tb += 8) {
        // produce tokens tb+16 .. tb+23 (warp0 even, warp1 odd; pad-safe)
        #pragma unroll
        for (int w = 0; w < 4; w++) {
            const int tok = tb + 16 + 2 * w + (tid >> 5);
            const int ps  = tok & (RING - 1);
            *(float2*)&smk[ps][2 * lane] = *(const float2*)&hb[tok * 64 + 2 * lane];
        }
        if (tid < 8) {
            const int tok = tb + 16 + tid;
            const int ps  = tok & (RING - 1);
            *(float4*)&smaux[ps][0] = *(const float4*)&gga[tok * 4];
            smaux[ps][4] = idb[tok];
        }
        #pragma unroll
        for (int u = 0; u < 8; u++) step(tb + u, u);
        __syncthreads();
    }
    // tail steps 2040..2046 (ring already holds tokens through 2055; the
    // lookahead dots past 2046 produce values that are never consumed)
    #pragma unroll
    for (int u = 0; u < 7; u++) step(2040 + u, u);

    // ctx = M_final . k_2047  (token 2047 lives at slot 31)
    {
        const ull* kq = (const ull*)&smk[2047 & (RING - 1)][c8 * 8];
        ull a0 = ffma2(M[0], kq[0], 0ull);
        ull a1 = ffma2(M[1], kq[1], 0ull);
        a0 = ffma2(M[2], kq[2], a0);
        a1 = ffma2(M[3], kq[3], a1);
        float lo, hi;
        funpack2(fadd2(a0, a1), lo, hi);
        float c = lo + hi;
        c += __shfl_xor_sync(0xffffffffu, c, 1);
        c += __shfl_xor_sync(0xffffffffu, c, 2);
        c += __shfl_xor_sync(0xffffffffu, c, 4);
        if (c8 == 0) g_ctx[bb * 64 + e] = c;
    }
}

// ---------------------------------------------------------------
// Phase 3: out = (ctx @ Wr + br) @ Wo + bo
// ---------------------------------------------------------------
__global__ __launch_bounds__(64) void proj_kernel(
    const float* __restrict__ Wr, const float* __restrict__ br,
    const float* __restrict__ Wo, const float* __restrict__ bo,
    float* __restrict__ out)
{
    __shared__ float cs[64], rs[64];
    const int b   = blockIdx.x;
    const int tid = threadIdx.x;
    cs[tid] = g_ctx[b * 64 + tid];
    __syncthreads();
    float rr = br[tid];
    #pragma unroll 8
    for (int j = 0; j < 64; j++) rr = fmaf(cs[j], Wr[j * 64 + tid], rr);
    rs[tid] = rr;
    __syncthreads();
    float o = bo[tid];
    #pragma unroll 8
    for (int j = 0; j < 64; j++) o = fmaf(rs[j], Wo[j * 64 + tid], o);
    out[b * 64 + tid] = o;
}

// ---------------------------------------------------------------
extern "C" void kernel_launch(void* const* d_in, const int* in_sizes, int n_in,
                              void* d_out, int out_size)
{
    const int*   seq   = (const int*)  d_in[0];
    const float* embed = (const float*)d_in[1];
    const float* W1    = (const float*)d_in[2];
    const float* b1    = (const float*)d_in[3];
    const float* W2    = (const float*)d_in[4];
    const float* b2    = (const float*)d_in[5];
    const float* gamma = (const float*)d_in[6];
    const float* beta  = (const float*)d_in[7];
    const float* Wr    = (const float*)d_in[8];
    const float* br    = (const float*)d_in[9];
    const float* Wo    = (const float*)d_in[10];
    const float* bo    = (const float*)d_in[11];
    float* out = (float*)d_out;

    (void)in_sizes; (void)n_in; (void)out_size;

    cudaFuncSetAttribute(phase1_kernel,
                         cudaFuncAttributeMaxDynamicSharedMemorySize, 65536);
    phase1_kernel<<<296, 256, 65536>>>(seq, embed, W1, b1, W2, b2, gamma, beta);
    gram_kernel<<<NTOK / 8, 256>>>();
    scan_kernel<<<BATCH * 8, 64>>>();
    proj_kernel<<<BATCH, 64>>>(Wr, br, Wo, bo, out);
}

// round 10
// speedup vs baseline: 4.5136x; 1.0609x over previous
#include <cuda_runtime.h>

#define HD    64
#define LSEQ  2048
#define BATCH 16
#define NTOK  (BATCH * LSEQ)
#define RING  32

typedef unsigned long long ull;

// Scratch (device globals, zero-initialized; pad regions never written -> stay 0)
__device__ float g_h[(NTOK + 16) * HD];   // post-LN hidden states (+pad)
__device__ float g_invd[NTOK + 16];       // 1 / (||h||^2 + 1e-6)
__device__ float g_gram[(NTOK + 16) * 8]; // per token: g_1..g_7 (g_j = k_{t-j}.k_t), invd
__device__ float g_ctx[BATCH * HD];       // ctx = M_final . q

// ---------------- packed f32x2 helpers (sm_103a) ----------------
__device__ __forceinline__ ull ffma2(ull a, ull b, ull c) {
    ull d;
    asm("fma.rn.f32x2 %0, %1, %2, %3;" : "=l"(d) : "l"(a), "l"(b), "l"(c));
    return d;
}
__device__ __forceinline__ ull fadd2(ull a, ull b) {
    ull d;
    asm("add.rn.f32x2 %0, %1, %2;" : "=l"(d) : "l"(a), "l"(b));
    return d;
}
__device__ __forceinline__ ull fpack2(float lo, float hi) {
    ull d;
    asm("mov.b64 %0, {%1, %2};" : "=l"(d) : "f"(lo), "f"(hi));
    return d;
}
__device__ __forceinline__ void funpack2(ull v, float& lo, float& hi) {
    asm("mov.b64 {%0, %1}, %2;" : "=f"(lo), "=f"(hi) : "l"(v));
}

// ---------------------------------------------------------------
// Phase 1: h = LN(embed[seq] + MLP(embed[seq])), plus inv_denom.
// (unchanged — known good)
// ---------------------------------------------------------------
__global__ __launch_bounds__(256) void phase1_kernel(
    const int*   __restrict__ seq,
    const float* __restrict__ embed,
    const float* __restrict__ W1,
    const float* __restrict__ b1,
    const float* __restrict__ W2,
    const float* __restrict__ b2,
    const float* __restrict__ gamma,
    const float* __restrict__ beta)
{
    extern __shared__ float dsm[];
    float* W1s = dsm;            // 64*128
    float* W2s = dsm + 64 * 128; // 128*64

    __shared__ __align__(16) float b1s[128];
    __shared__ float b2s[64], gs[64], bs[64];
    __shared__ __align__(16) float hs[8][64];
    __shared__ __align__(16) float as_[8][128];

    const int tid = threadIdx.x;
    for (int i = tid; i < 64 * 128; i += 256) W1s[i] = W1[i];
    for (int i = tid; i < 128 * 64; i += 256) W2s[i] = W2[i];
    if (tid < 128) b1s[tid] = b1[tid];
    if (tid < 64) { b2s[tid] = b2[tid]; gs[tid] = gamma[tid]; bs[tid] = beta[tid]; }
    __syncthreads();

    const int w    = tid >> 5;
    const int lane = tid & 31;
    const int gw   = blockIdx.x * 8 + w;
    const int nw   = gridDim.x * 8;

    for (int tok = gw; tok < NTOK; tok += nw) {
        const int v = seq[tok];
        const float h0 = embed[v * 64 + lane];
        const float h1 = embed[v * 64 + 32 + lane];
        hs[w][lane]      = h0;
        hs[w][lane + 32] = h1;
        __syncwarp();

        float4 a4 = *(const float4*)&b1s[lane * 4];
        #pragma unroll 16
        for (int j = 0; j < 64; j++) {
            const float  hj = hs[w][j];
            const float4 w4 = *(const float4*)&W1s[j * 128 + lane * 4];
            a4.x = fmaf(hj, w4.x, a4.x);
            a4.y = fmaf(hj, w4.y, a4.y);
            a4.z = fmaf(hj, w4.z, a4.z);
            a4.w = fmaf(hj, w4.w, a4.w);
        }
        a4.x = fmaxf(a4.x, 0.f); a4.y = fmaxf(a4.y, 0.f);
        a4.z = fmaxf(a4.z, 0.f); a4.w = fmaxf(a4.w, 0.f);
        *(float4*)&as_[w][lane * 4] = a4;
        __syncwarp();

        float f0 = b2s[2 * lane], f1 = b2s[2 * lane + 1];
        #pragma unroll 16
        for (int m = 0; m < 128; m++) {
            const float  am = as_[w][m];
            const float2 w2 = *(const float2*)&W2s[m * 64 + lane * 2];
            f0 = fmaf(am, w2.x, f0);
            f1 = fmaf(am, w2.y, f1);
        }

        float x0 = hs[w][2 * lane]     + f0;
        float x1 = hs[w][2 * lane + 1] + f1;

        float s = x0 + x1;
        #pragma unroll
        for (int o = 16; o > 0; o >>= 1) s += __shfl_xor_sync(0xffffffffu, s, o);
        const float mu = s * (1.0f / 64.0f);
        const float d0 = x0 - mu, d1 = x1 - mu;
        float sq = d0 * d0 + d1 * d1;
        #pragma unroll
        for (int o = 16; o > 0; o >>= 1) sq += __shfl_xor_sync(0xffffffffu, sq, o);
        const float rstd = rsqrtf(sq * (1.0f / 64.0f) + 1e-5f);

        const float y0 = d0 * rstd * gs[2 * lane]     + bs[2 * lane];
        const float y1 = d1 * rstd * gs[2 * lane + 1] + bs[2 * lane + 1];
        *(float2*)&g_h[tok * 64 + 2 * lane] = make_float2(y0, y1);

        float ss = y0 * y0 + y1 * y1;
        #pragma unroll
        for (int o = 16; o > 0; o >>= 1) ss += __shfl_xor_sync(0xffffffffu, ss, o);
        if (lane == 0) g_invd[tok] = 1.0f / (ss + 1e-6f);
        __syncwarp();
    }
}

// ---------------------------------------------------------------
// Phase 1.5: Gram lookahead g_j[t] = k_{t-j} . k_t (j=1..7) + invd,
// packed 8 floats per token. Masked at sequence starts. Warp/token.
// ---------------------------------------------------------------
__global__ __launch_bounds__(256) void gram_kernel()
{
    const int wid  = (blockIdx.x * 256 + threadIdx.x) >> 5;
    const int lane = threadIdx.x & 31;
    if (wid >= NTOK) return;
    const int t   = wid;
    const int pos = t & (LSEQ - 1);

    const ull kt = *(const ull*)&g_h[t * 64 + 2 * lane];
    float res[7];
    #pragma unroll
    for (int j = 1; j <= 7; j++) {
        ull kj = 0ull;
        if (pos >= j) kj = *(const ull*)&g_h[(t - j) * 64 + 2 * lane];
        const ull a = ffma2(kt, kj, 0ull);
        float lo, hi;
        funpack2(a, lo, hi);
        float s = lo + hi;
        #pragma unroll
        for (int o = 16; o > 0; o >>= 1) s += __shfl_xor_sync(0xffffffffu, s, o);
        res[j - 1] = s;
    }
    if (lane == 0) {
        *(float4*)&g_gram[t * 8]     = make_float4(res[0], res[1], res[2], res[3]);
        *(float4*)&g_gram[t * 8 + 4] = make_float4(res[4], res[5], res[6], g_invd[t]);
    }
}

// ---------------------------------------------------------------
// Phase 2: delta-rule scan blocked into rank-8 windows.
// Grid 128 = 16 batches x 8 row-groups; 64 threads (2 warps).
// Thread (r, c8): row e = rg*8+r, cols [8*c8, 8*c8+8) (4 f32x2 regs).
// Per window tb (8 steps):
//   dots:   c_u = M . k_{tb+u}          (8 independent dot+reduce chains)
//   serial: S_u = c_u + sum_{j=1..u} dv_{u-j} g_j[tb+u];  dv_u = ke_u - iv_u*S_u
//   update: M  += sum_u dv_u * k_{tb+u} (rank-8, full ILP)
// Tail window: 7 steps; S_7 (token 2047) IS ctx = M_final . q.
// ---------------------------------------------------------------
__global__ __launch_bounds__(64, 1) void scan_kernel()
{
    __shared__ __align__(16) float smk[RING][64];
    __shared__ __align__(16) float smaux[RING][8];  // g1..g7, invd

    const int bb   = blockIdx.x >> 3;
    const int rg   = blockIdx.x & 7;
    const int tid  = threadIdx.x;
    const int lane = tid & 31;
    const int r    = tid >> 3;     // row within group 0..7
    const int c8   = tid & 7;      // column eighth
    const int e    = rg * 8 + r;

    const float* __restrict__ hb  = g_h    + (size_t)bb * LSEQ * HD;
    const float* __restrict__ gga = g_gram + (size_t)bb * LSEQ * 8;

    ull M[4];
    #pragma unroll
    for (int i = 0; i < 4; i++) M[i] = 0ull;

    // prologue: fill ring with tokens 0..15 (+aux)
    #pragma unroll
    for (int w = 0; w < 8; w++) {
        const int tok = 2 * w + (tid >> 5);
        *(float2*)&smk[tok][2 * lane] = *(const float2*)&hb[tok * 64 + 2 * lane];
    }
    if (tid < 16) {
        *(float4*)&smaux[tid][0] = *(const float4*)&gga[tid * 8];
        *(float4*)&smaux[tid][4] = *(const float4*)&gga[tid * 8 + 4];
    }
    __syncthreads();

    float c[8], dv[8];

    #pragma unroll 1
    for (int tb = 0; tb < 2040; tb += 8) {
        // prefetch tokens tb+16 .. tb+23 (pad-safe)
        #pragma unroll
        for (int w = 0; w < 4; w++) {
            const int tok = tb + 16 + 2 * w + (tid >> 5);
            const int ps  = tok & (RING - 1);
            *(float2*)&smk[ps][2 * lane] = *(const float2*)&hb[tok * 64 + 2 * lane];
        }
        if (tid < 8) {
            const int tok = tb + 16 + tid;
            const int ps  = tok & (RING - 1);
            *(float4*)&smaux[ps][0] = *(const float4*)&gga[tok * 8];
            *(float4*)&smaux[ps][4] = *(const float4*)&gga[tok * 8 + 4];
        }

        // ---- dots: c_u = M . k_{tb+u} (8 independent) ----
        #pragma unroll
        for (int u = 0; u < 8; u++) {
            const ull* kd = (const ull*)&smk[(tb + u) & (RING - 1)][c8 * 8];
            ull a0 = ffma2(M[0], kd[0], 0ull);
            ull a1 = ffma2(M[1], kd[1], 0ull);
            a0 = ffma2(M[2], kd[2], a0);
            a1 = ffma2(M[3], kd[3], a1);
            float lo, hi;
            funpack2(fadd2(a0, a1), lo, hi);
            c[u] = lo + hi;
        }
        #pragma unroll
        for (int u = 0; u < 8; u++) c[u] += __shfl_xor_sync(0xffffffffu, c[u], 1);
        #pragma unroll
        for (int u = 0; u < 8; u++) c[u] += __shfl_xor_sync(0xffffffffu, c[u], 2);
        #pragma unroll
        for (int u = 0; u < 8; u++) c[u] += __shfl_xor_sync(0xffffffffu, c[u], 4);

        // ---- serial phase (per-row scalars; chain = 2 FMA/step) ----
        #pragma unroll
        for (int u = 0; u < 8; u++) {
            const int sl = (tb + u) & (RING - 1);
            const float  ke = smk[sl][e];
            const float4 gA = *(const float4*)&smaux[sl][0];
            const float4 gB = *(const float4*)&smaux[sl][4];
            float S = c[u];
            if (u >= 7) S = fmaf(dv[u - 7], gB.z, S);
            if (u >= 6) S = fmaf(dv[u - 6], gB.y, S);
            if (u >= 5) S = fmaf(dv[u - 5], gB.x, S);
            if (u >= 4) S = fmaf(dv[u - 4], gA.w, S);
            if (u >= 3) S = fmaf(dv[u - 3], gA.z, S);
            if (u >= 2) S = fmaf(dv[u - 2], gA.y, S);
            if (u >= 1) S = fmaf(dv[u - 1], gA.x, S);
            dv[u] = fmaf(-gB.w, S, ke);
        }

        // ---- rank-8 M update (full ILP) ----
        #pragma unroll
        for (int u = 0; u < 8; u++) {
            const ull dvp = fpack2(dv[u], dv[u]);
            const ull* kq = (const ull*)&smk[(tb + u) & (RING - 1)][c8 * 8];
            M[0] = ffma2(dvp, kq[0], M[0]);
            M[1] = ffma2(dvp, kq[1], M[1]);
            M[2] = ffma2(dvp, kq[2], M[2]);
            M[3] = ffma2(dvp, kq[3], M[3]);
        }
        __syncthreads();
    }

    // ---- tail window tb=2040: steps 2040..2046, then ctx at token 2047 ----
    {
        const int tb = 2040;
        #pragma unroll
        for (int u = 0; u < 8; u++) {
            const ull* kd = (const ull*)&smk[(tb + u) & (RING - 1)][c8 * 8];
            ull a0 = ffma2(M[0], kd[0], 0ull);
            ull a1 = ffma2(M[1], kd[1], 0ull);
            a0 = ffma2(M[2], kd[2], a0);
            a1 = ffma2(M[3], kd[3], a1);
            float lo, hi;
            funpack2(fadd2(a0, a1), lo, hi);
            c[u] = lo + hi;
        }
        #pragma unroll
        for (int u = 0; u < 8; u++) c[u] += __shfl_xor_sync(0xffffffffu, c[u], 1);
        #pragma unroll
        for (int u = 0; u < 8; u++) c[u] += __shfl_xor_sync(0xffffffffu, c[u], 2);
        #pragma unroll
        for (int u = 0; u < 8; u++) c[u] += __shfl_xor_sync(0xffffffffu, c[u], 4);

        #pragma unroll
        for (int u = 0; u < 7; u++) {
            const int sl = (tb + u) & (RING - 1);
            const float  ke = smk[sl][e];
            const float4 gA = *(const float4*)&smaux[sl][0];
            const float4 gB = *(const float4*)&smaux[sl][4];
            float S = c[u];
            if (u >= 6) S = fmaf(dv[u - 6], gB.y, S);
            if (u >= 5) S = fmaf(dv[u - 5], gB.x, S);
            if (u >= 4) S = fmaf(dv[u - 4], gA.w, S);
            if (u >= 3) S = fmaf(dv[u - 3], gA.z, S);
            if (u >= 2) S = fmaf(dv[u - 2], gA.y, S);
            if (u >= 1) S = fmaf(dv[u - 1], gA.x, S);
            dv[u] = fmaf(-gB.w, S, ke);
        }

        // ctx[e] = c_7 + sum_{j=1..7} dv_{7-j} * g_j[2047]   (token 2047 = slot 31)
        const float4 gA = *(const float4*)&smaux[2047 & (RING - 1)][0];
        const float4 gB = *(const float4*)&smaux[2047 & (RING - 1)][4];
        float S = c[7];
        S = fmaf(dv[0], gB.z, S);
        S = fmaf(dv[1], gB.y, S);
        S = fmaf(dv[2], gB.x, S);
        S = fmaf(dv[3], gA.w, S);
        S = fmaf(dv[4], gA.z, S);
        S = fmaf(dv[5], gA.y, S);
        S = fmaf(dv[6], gA.x, S);
        if (c8 == 0) g_ctx[bb * 64 + e] = S;
    }
}

// ---------------------------------------------------------------
// Phase 3: out = (ctx @ Wr + br) @ Wo + bo
// ---------------------------------------------------------------
__global__ __launch_bounds__(64) void proj_kernel(
    const float* __restrict__ Wr, const float* __restrict__ br,
    const float* __restrict__ Wo, const float* __restrict__ bo,
    float* __restrict__ out)
{
    __shared__ float cs[64], rs[64];
    const int b   = blockIdx.x;
    const int tid = threadIdx.x;
    cs[tid] = g_ctx[b * 64 + tid];
    __syncthreads();
    float rr = br[tid];
    #pragma unroll 8
    for (int j = 0; j < 64; j++) rr = fmaf(cs[j], Wr[j * 64 + tid], rr);
    rs[tid] = rr;
    __syncthreads();
    float o = bo[tid];
    #pragma unroll 8
    for (int j = 0; j < 64; j++) o = fmaf(rs[j], Wo[j * 64 + tid], o);
    out[b * 64 + tid] = o;
}

// ---------------------------------------------------------------
extern "C" void kernel_launch(void* const* d_in, const int* in_sizes, int n_in,
                              void* d_out, int out_size)
{
    const int*   seq   = (const int*)  d_in[0];
    const float* embed = (const float*)d_in[1];
    const float* W1    = (const float*)d_in[2];
    const float* b1    = (const float*)d_in[3];
    const float* W2    = (const float*)d_in[4];
    const float* b2    = (const float*)d_in[5];
    const float* gamma = (const float*)d_in[6];
    const float* beta  = (const float*)d_in[7];
    const float* Wr    = (const float*)d_in[8];
    const float* br    = (const float*)d_in[9];
    const float* Wo    = (const float*)d_in[10];
    const float* bo    = (const float*)d_in[11];
    float* out = (float*)d_out;

    (void)in_sizes; (void)n_in; (void)out_size;

    cudaFuncSetAttribute(phase1_kernel,
                         cudaFuncAttributeMaxDynamicSharedMemorySize, 65536);
    phase1_kernel<<<296, 256, 65536>>>(seq, embed, W1, b1, W2, b2, gamma, beta);
    gram_kernel<<<NTOK / 8, 256>>>();
    scan_kernel<<<BATCH * 8, 64>>>();
    proj_kernel<<<BATCH, 64>>>(Wr, br, Wo, bo, out);
}

// round 11
// speedup vs baseline: 5.2457x; 1.1622x over previous
#include <cuda_runtime.h>

#define HD    64
#define LSEQ  2048
#define BATCH 16
#define NTOK  (BATCH * LSEQ)
#define RING  32

typedef unsigned long long ull;

// Scratch (device globals, zero-initialized; pad regions never written -> stay 0)
__device__ float g_h[(NTOK + 16) * HD];   // post-LN hidden states (+pad)
__device__ float g_invd[NTOK + 16];       // 1 / (||h||^2 + 1e-6)
__device__ float g_gram[(NTOK + 16) * 8]; // per token: g_1..g_7 (g_j = k_{t-j}.k_t), invd
__device__ float g_ctx[BATCH * HD];       // ctx = M_final . q

// ---------------- packed f32x2 helpers (sm_103a) ----------------
__device__ __forceinline__ ull ffma2(ull a, ull b, ull c) {
    ull d;
    asm("fma.rn.f32x2 %0, %1, %2, %3;" : "=l"(d) : "l"(a), "l"(b), "l"(c));
    return d;
}
__device__ __forceinline__ ull fadd2(ull a, ull b) {
    ull d;
    asm("add.rn.f32x2 %0, %1, %2;" : "=l"(d) : "l"(a), "l"(b));
    return d;
}
__device__ __forceinline__ ull fpack2(float lo, float hi) {
    ull d;
    asm("mov.b64 %0, {%1, %2};" : "=l"(d) : "f"(lo), "f"(hi));
    return d;
}
__device__ __forceinline__ void funpack2(ull v, float& lo, float& hi) {
    asm("mov.b64 {%0, %1}, %2;" : "=f"(lo), "=f"(hi) : "l"(v));
}

// ---------------------------------------------------------------
// Phase 1: h = LN(embed[seq] + MLP(embed[seq])), plus inv_denom.
// (unchanged — known good)
// ---------------------------------------------------------------
__global__ __launch_bounds__(256) void phase1_kernel(
    const int*   __restrict__ seq,
    const float* __restrict__ embed,
    const float* __restrict__ W1,
    const float* __restrict__ b1,
    const float* __restrict__ W2,
    const float* __restrict__ b2,
    const float* __restrict__ gamma,
    const float* __restrict__ beta)
{
    extern __shared__ float dsm[];
    float* W1s = dsm;            // 64*128
    float* W2s = dsm + 64 * 128; // 128*64

    __shared__ __align__(16) float b1s[128];
    __shared__ float b2s[64], gs[64], bs[64];
    __shared__ __align__(16) float hs[8][64];
    __shared__ __align__(16) float as_[8][128];

    const int tid = threadIdx.x;
    for (int i = tid; i < 64 * 128; i += 256) W1s[i] = W1[i];
    for (int i = tid; i < 128 * 64; i += 256) W2s[i] = W2[i];
    if (tid < 128) b1s[tid] = b1[tid];
    if (tid < 64) { b2s[tid] = b2[tid]; gs[tid] = gamma[tid]; bs[tid] = beta[tid]; }
    __syncthreads();

    const int w    = tid >> 5;
    const int lane = tid & 31;
    const int gw   = blockIdx.x * 8 + w;
    const int nw   = gridDim.x * 8;

    for (int tok = gw; tok < NTOK; tok += nw) {
        const int v = seq[tok];
        const float h0 = embed[v * 64 + lane];
        const float h1 = embed[v * 64 + 32 + lane];
        hs[w][lane]      = h0;
        hs[w][lane + 32] = h1;
        __syncwarp();

        float4 a4 = *(const float4*)&b1s[lane * 4];
        #pragma unroll 16
        for (int j = 0; j < 64; j++) {
            const float  hj = hs[w][j];
            const float4 w4 = *(const float4*)&W1s[j * 128 + lane * 4];
            a4.x = fmaf(hj, w4.x, a4.x);
            a4.y = fmaf(hj, w4.y, a4.y);
            a4.z = fmaf(hj, w4.z, a4.z);
            a4.w = fmaf(hj, w4.w, a4.w);
        }
        a4.x = fmaxf(a4.x, 0.f); a4.y = fmaxf(a4.y, 0.f);
        a4.z = fmaxf(a4.z, 0.f); a4.w = fmaxf(a4.w, 0.f);
        *(float4*)&as_[w][lane * 4] = a4;
        __syncwarp();

        float f0 = b2s[2 * lane], f1 = b2s[2 * lane + 1];
        #pragma unroll 16
        for (int m = 0; m < 128; m++) {
            const float  am = as_[w][m];
            const float2 w2 = *(const float2*)&W2s[m * 64 + lane * 2];
            f0 = fmaf(am, w2.x, f0);
            f1 = fmaf(am, w2.y, f1);
        }

        float x0 = hs[w][2 * lane]     + f0;
        float x1 = hs[w][2 * lane + 1] + f1;

        float s = x0 + x1;
        #pragma unroll
        for (int o = 16; o > 0; o >>= 1) s += __shfl_xor_sync(0xffffffffu, s, o);
        const float mu = s * (1.0f / 64.0f);
        const float d0 = x0 - mu, d1 = x1 - mu;
        float sq = d0 * d0 + d1 * d1;
        #pragma unroll
        for (int o = 16; o > 0; o >>= 1) sq += __shfl_xor_sync(0xffffffffu, sq, o);
        const float rstd = rsqrtf(sq * (1.0f / 64.0f) + 1e-5f);

        const float y0 = d0 * rstd * gs[2 * lane]     + bs[2 * lane];
        const float y1 = d1 * rstd * gs[2 * lane + 1] + bs[2 * lane + 1];
        *(float2*)&g_h[tok * 64 + 2 * lane] = make_float2(y0, y1);

        float ss = y0 * y0 + y1 * y1;
        #pragma unroll
        for (int o = 16; o > 0; o >>= 1) ss += __shfl_xor_sync(0xffffffffu, ss, o);
        if (lane == 0) g_invd[tok] = 1.0f / (ss + 1e-6f);
        __syncwarp();
    }
}

// ---------------------------------------------------------------
// Phase 1.5: Gram lookahead g_j[t] = k_{t-j} . k_t (j=1..7) + invd,
// packed 8 floats per token. Masked at sequence starts. Warp/token.
// ---------------------------------------------------------------
__global__ __launch_bounds__(256) void gram_kernel()
{
    const int wid  = (blockIdx.x * 256 + threadIdx.x) >> 5;
    const int lane = threadIdx.x & 31;
    if (wid >= NTOK) return;
    const int t   = wid;
    const int pos = t & (LSEQ - 1);

    const ull kt = *(const ull*)&g_h[t * 64 + 2 * lane];
    float res[7];
    #pragma unroll
    for (int j = 1; j <= 7; j++) {
        ull kj = 0ull;
        if (pos >= j) kj = *(const ull*)&g_h[(t - j) * 64 + 2 * lane];
        const ull a = ffma2(kt, kj, 0ull);
        float lo, hi;
        funpack2(a, lo, hi);
        float s = lo + hi;
        #pragma unroll
        for (int o = 16; o > 0; o >>= 1) s += __shfl_xor_sync(0xffffffffu, s, o);
        res[j - 1] = s;
    }
    if (lane == 0) {
        *(float4*)&g_gram[t * 8]     = make_float4(res[0], res[1], res[2], res[3]);
        *(float4*)&g_gram[t * 8 + 4] = make_float4(res[4], res[5], res[6], g_invd[t]);
    }
}

// ---------------------------------------------------------------
// Phase 2: delta-rule scan, rank-8 windows, SOFTWARE-PIPELINED dots.
// Grid 128 = 16 batches x 8 row-groups; 64 threads (2 warps).
// Thread (r, c8): row e = rg*8+r, cols [8*c8, 8*c8+8) (4 f32x2 regs).
// Iteration for window tb (c[] carried from previous iteration):
//   serial: S_u = c_u + sum_{j=1..u} dv_{u-j} g_j;  dv_u = ke_u - iv_u*S_u
//   update: M  += sum_u dv_u * k_{tb+u}
//   dots:   c_u = M . k_{tb+8+u}      (for NEXT window; latency hidden by
//                                      barrier + next serial phase)
//   prefetch tokens tb+24..31; one __syncthreads.
// Tail (window 2040): 7 serial steps; ctx = corrected c[7] at token 2047.
// ---------------------------------------------------------------
__global__ __launch_bounds__(64, 1) void scan_kernel()
{
    __shared__ __align__(16) float smk[RING][64];
    __shared__ __align__(16) float smaux[RING][8];  // g1..g7, invd

    const int bb   = blockIdx.x >> 3;
    const int rg   = blockIdx.x & 7;
    const int tid  = threadIdx.x;
    const int lane = tid & 31;
    const int r    = tid >> 3;     // row within group 0..7
    const int c8   = tid & 7;      // column eighth
    const int e    = rg * 8 + r;

    const float* __restrict__ hb  = g_h    + (size_t)bb * LSEQ * HD;
    const float* __restrict__ gga = g_gram + (size_t)bb * LSEQ * 8;

    ull M[4];
    #pragma unroll
    for (int i = 0; i < 4; i++) M[i] = 0ull;

    float c[8], dv[8];
    #pragma unroll
    for (int i = 0; i < 8; i++) c[i] = 0.0f;   // M_0 . k = 0 for window 0

    // prologue: fill ring with tokens 0..23 (+aux)
    #pragma unroll
    for (int w = 0; w < 12; w++) {
        const int tok = 2 * w + (tid >> 5);
        *(float2*)&smk[tok][2 * lane] = *(const float2*)&hb[tok * 64 + 2 * lane];
    }
    if (tid < 24) {
        *(float4*)&smaux[tid][0] = *(const float4*)&gga[tid * 8];
        *(float4*)&smaux[tid][4] = *(const float4*)&gga[tid * 8 + 4];
    }
    __syncthreads();

    #pragma unroll 1
    for (int tb = 0; tb <= 2032; tb += 8) {
        // ---- serial phase (window tb; c[] from previous iteration's dots) ----
        #pragma unroll
        for (int u = 0; u < 8; u++) {
            const int sl = (tb + u) & (RING - 1);
            const float  ke = smk[sl][e];
            const float4 gA = *(const float4*)&smaux[sl][0];
            const float4 gB = *(const float4*)&smaux[sl][4];
            float S = c[u];
            if (u >= 7) S = fmaf(dv[u - 7], gB.z, S);
            if (u >= 6) S = fmaf(dv[u - 6], gB.y, S);
            if (u >= 5) S = fmaf(dv[u - 5], gB.x, S);
            if (u >= 4) S = fmaf(dv[u - 4], gA.w, S);
            if (u >= 3) S = fmaf(dv[u - 3], gA.z, S);
            if (u >= 2) S = fmaf(dv[u - 2], gA.y, S);
            if (u >= 1) S = fmaf(dv[u - 1], gA.x, S);
            dv[u] = fmaf(-gB.w, S, ke);
        }

        // ---- rank-8 M update (full ILP) ----
        #pragma unroll
        for (int u = 0; u < 8; u++) {
            const ull dvp = fpack2(dv[u], dv[u]);
            const ulonglong2* kq =
                (const ulonglong2*)&smk[(tb + u) & (RING - 1)][c8 * 8];
            const ulonglong2 k0 = kq[0], k1 = kq[1];
            M[0] = ffma2(dvp, k0.x, M[0]);
            M[1] = ffma2(dvp, k0.y, M[1]);
            M[2] = ffma2(dvp, k1.x, M[2]);
            M[3] = ffma2(dvp, k1.y, M[3]);
        }

        // ---- dots for NEXT window: c_u = M . k_{tb+8+u} ----
        #pragma unroll
        for (int u = 0; u < 8; u++) {
            const ulonglong2* kd =
                (const ulonglong2*)&smk[(tb + 8 + u) & (RING - 1)][c8 * 8];
            const ulonglong2 k0 = kd[0], k1 = kd[1];
            ull a0 = ffma2(M[0], k0.x, 0ull);
            ull a1 = ffma2(M[1], k0.y, 0ull);
            a0 = ffma2(M[2], k1.x, a0);
            a1 = ffma2(M[3], k1.y, a1);
            float lo, hi;
            funpack2(fadd2(a0, a1), lo, hi);
            c[u] = lo + hi;
        }
        #pragma unroll
        for (int u = 0; u < 8; u++) c[u] += __shfl_xor_sync(0xffffffffu, c[u], 1);
        #pragma unroll
        for (int u = 0; u < 8; u++) c[u] += __shfl_xor_sync(0xffffffffu, c[u], 2);
        #pragma unroll
        for (int u = 0; u < 8; u++) c[u] += __shfl_xor_sync(0xffffffffu, c[u], 4);

        // ---- prefetch tokens tb+24 .. tb+31 (pad-safe; read 2 iters later) ----
        #pragma unroll
        for (int w = 0; w < 4; w++) {
            const int tok = tb + 24 + 2 * w + (tid >> 5);
            const int ps  = tok & (RING - 1);
            *(float2*)&smk[ps][2 * lane] = *(const float2*)&hb[tok * 64 + 2 * lane];
        }
        if (tid < 8) {
            const int tok = tb + 24 + tid;
            const int ps  = tok & (RING - 1);
            *(float4*)&smaux[ps][0] = *(const float4*)&gga[tok * 8];
            *(float4*)&smaux[ps][4] = *(const float4*)&gga[tok * 8 + 4];
        }
        __syncthreads();
    }

    // ---- tail window tb=2040: 7 serial steps, then ctx at token 2047 ----
    {
        const int tb = 2040;
        #pragma unroll
        for (int u = 0; u < 7; u++) {
            const int sl = (tb + u) & (RING - 1);
            const float  ke = smk[sl][e];
            const float4 gA = *(const float4*)&smaux[sl][0];
            const float4 gB = *(const float4*)&smaux[sl][4];
            float S = c[u];
            if (u >= 6) S = fmaf(dv[u - 6], gB.y, S);
            if (u >= 5) S = fmaf(dv[u - 5], gB.x, S);
            if (u >= 4) S = fmaf(dv[u - 4], gA.w, S);
            if (u >= 3) S = fmaf(dv[u - 3], gA.z, S);
            if (u >= 2) S = fmaf(dv[u - 2], gA.y, S);
            if (u >= 1) S = fmaf(dv[u - 1], gA.x, S);
            dv[u] = fmaf(-gB.w, S, ke);
        }

        // ctx[e] = c_7 + sum_{j=1..7} dv_{7-j} * g_j[2047]
        const float4 gA = *(const float4*)&smaux[2047 & (RING - 1)][0];
        const float4 gB = *(const float4*)&smaux[2047 & (RING - 1)][4];
        float S = c[7];
        S = fmaf(dv[0], gB.z, S);
        S = fmaf(dv[1], gB.y, S);
        S = fmaf(dv[2], gB.x, S);
        S = fmaf(dv[3], gA.w, S);
        S = fmaf(dv[4], gA.z, S);
        S = fmaf(dv[5], gA.y, S);
        S = fmaf(dv[6], gA.x, S);
        if (c8 == 0) g_ctx[bb * 64 + e] = S;
    }
}

// ---------------------------------------------------------------
// Phase 3: out = (ctx @ Wr + br) @ Wo + bo
// ---------------------------------------------------------------
__global__ __launch_bounds__(64) void proj_kernel(
    const float* __restrict__ Wr, const float* __restrict__ br,
    const float* __restrict__ Wo, const float* __restrict__ bo,
    float* __restrict__ out)
{
    __shared__ float cs[64], rs[64];
    const int b   = blockIdx.x;
    const int tid = threadIdx.x;
    cs[tid] = g_ctx[b * 64 + tid];
    __syncthreads();
    float rr = br[tid];
    #pragma unroll 8
    for (int j = 0; j < 64; j++) rr = fmaf(cs[j], Wr[j * 64 + tid], rr);
    rs[tid] = rr;
    __syncthreads();
    float o = bo[tid];
    #pragma unroll 8
    for (int j = 0; j < 64; j++) o = fmaf(rs[j], Wo[j * 64 + tid], o);
    out[b * 64 + tid] = o;
}

// ---------------------------------------------------------------
extern "C" void kernel_launch(void* const* d_in, const int* in_sizes, int n_in,
                              void* d_out, int out_size)
{
    const int*   seq   = (const int*)  d_in[0];
    const float* embed = (const float*)d_in[1];
    const float* W1    = (const float*)d_in[2];
    const float* b1    = (const float*)d_in[3];
    const float* W2    = (const float*)d_in[4];
    const float* b2    = (const float*)d_in[5];
    const float* gamma = (const float*)d_in[6];
    const float* beta  = (const float*)d_in[7];
    const float* Wr    = (const float*)d_in[8];
    const float* br    = (const float*)d_in[9];
    const float* Wo    = (const float*)d_in[10];
    const float* bo    = (const float*)d_in[11];
    float* out = (float*)d_out;

    (void)in_sizes; (void)n_in; (void)out_size;

    cudaFuncSetAttribute(phase1_kernel,
                         cudaFuncAttributeMaxDynamicSharedMemorySize, 65536);
    phase1_kernel<<<296, 256, 65536>>>(seq, embed, W1, b1, W2, b2, gamma, beta);
    gram_kernel<<<NTOK / 8, 256>>>();
    scan_kernel<<<BATCH * 8, 64>>>();
    proj_kernel<<<BATCH, 64>>>(Wr, br, Wo, bo, out);
}

// round 12
// speedup vs baseline: 5.3800x; 1.0256x over previous
#include <cuda_runtime.h>

#define HD    64
#define LSEQ  2048
#define BATCH 16
#define NTOK  (BATCH * LSEQ)
#define RING  32

typedef unsigned long long ull;

// Scratch (device globals, zero-initialized; pad regions never written -> stay 0)
__device__ float g_h[(NTOK + 16) * HD];   // post-LN hidden states (+pad)
__device__ float g_gram[(NTOK + 16) * 8]; // per token: g_1..g_7 (g_j = k_{t-j}.k_t), invd
__device__ float g_ctx[BATCH * HD];       // ctx = M_final . q

// ---------------- packed f32x2 helpers (sm_103a) ----------------
__device__ __forceinline__ ull ffma2(ull a, ull b, ull c) {
    ull d;
    asm("fma.rn.f32x2 %0, %1, %2, %3;" : "=l"(d) : "l"(a), "l"(b), "l"(c));
    return d;
}
__device__ __forceinline__ ull fadd2(ull a, ull b) {
    ull d;
    asm("add.rn.f32x2 %0, %1, %2;" : "=l"(d) : "l"(a), "l"(b));
    return d;
}
__device__ __forceinline__ ull fpack2(float lo, float hi) {
    ull d;
    asm("mov.b64 %0, {%1, %2};" : "=l"(d) : "f"(lo), "f"(hi));
    return d;
}
__device__ __forceinline__ void funpack2(ull v, float& lo, float& hi) {
    asm("mov.b64 {%0, %1}, %2;" : "=f"(lo), "=f"(hi) : "l"(v));
}

// ---------------------------------------------------------------
// Phase 1: h = LN(embed[seq] + MLP(embed[seq])).
// One warp per token. W1/W2 live in dynamic shared (64 KB).
// (invd computation moved to gram_kernel)
// ---------------------------------------------------------------
__global__ __launch_bounds__(256) void phase1_kernel(
    const int*   __restrict__ seq,
    const float* __restrict__ embed,
    const float* __restrict__ W1,
    const float* __restrict__ b1,
    const float* __restrict__ W2,
    const float* __restrict__ b2,
    const float* __restrict__ gamma,
    const float* __restrict__ beta)
{
    extern __shared__ float dsm[];
    float* W1s = dsm;            // 64*128
    float* W2s = dsm + 64 * 128; // 128*64

    __shared__ __align__(16) float b1s[128];
    __shared__ float b2s[64], gs[64], bs[64];
    __shared__ __align__(16) float hs[8][64];
    __shared__ __align__(16) float as_[8][128];

    const int tid = threadIdx.x;
    for (int i = tid; i < 64 * 128; i += 256) W1s[i] = W1[i];
    for (int i = tid; i < 128 * 64; i += 256) W2s[i] = W2[i];
    if (tid < 128) b1s[tid] = b1[tid];
    if (tid < 64) { b2s[tid] = b2[tid]; gs[tid] = gamma[tid]; bs[tid] = beta[tid]; }
    __syncthreads();

    const int w    = tid >> 5;
    const int lane = tid & 31;
    const int gw   = blockIdx.x * 8 + w;
    const int nw   = gridDim.x * 8;

    for (int tok = gw; tok < NTOK; tok += nw) {
        const int v = seq[tok];
        const float h0 = embed[v * 64 + lane];
        const float h1 = embed[v * 64 + 32 + lane];
        hs[w][lane]      = h0;
        hs[w][lane + 32] = h1;
        __syncwarp();

        float4 a4 = *(const float4*)&b1s[lane * 4];
        #pragma unroll 16
        for (int j = 0; j < 64; j++) {
            const float  hj = hs[w][j];
            const float4 w4 = *(const float4*)&W1s[j * 128 + lane * 4];
            a4.x = fmaf(hj, w4.x, a4.x);
            a4.y = fmaf(hj, w4.y, a4.y);
            a4.z = fmaf(hj, w4.z, a4.z);
            a4.w = fmaf(hj, w4.w, a4.w);
        }
        a4.x = fmaxf(a4.x, 0.f); a4.y = fmaxf(a4.y, 0.f);
        a4.z = fmaxf(a4.z, 0.f); a4.w = fmaxf(a4.w, 0.f);
        *(float4*)&as_[w][lane * 4] = a4;
        __syncwarp();

        float f0 = b2s[2 * lane], f1 = b2s[2 * lane + 1];
        #pragma unroll 16
        for (int m = 0; m < 128; m++) {
            const float  am = as_[w][m];
            const float2 w2 = *(const float2*)&W2s[m * 64 + lane * 2];
            f0 = fmaf(am, w2.x, f0);
            f1 = fmaf(am, w2.y, f1);
        }

        float x0 = hs[w][2 * lane]     + f0;
        float x1 = hs[w][2 * lane + 1] + f1;

        float s = x0 + x1;
        #pragma unroll
        for (int o = 16; o > 0; o >>= 1) s += __shfl_xor_sync(0xffffffffu, s, o);
        const float mu = s * (1.0f / 64.0f);
        const float d0 = x0 - mu, d1 = x1 - mu;
        float sq = d0 * d0 + d1 * d1;
        #pragma unroll
        for (int o = 16; o > 0; o >>= 1) sq += __shfl_xor_sync(0xffffffffu, sq, o);
        const float rstd = rsqrtf(sq * (1.0f / 64.0f) + 1e-5f);

        const float y0 = d0 * rstd * gs[2 * lane]     + bs[2 * lane];
        const float y1 = d1 * rstd * gs[2 * lane + 1] + bs[2 * lane + 1];
        *(float2*)&g_h[tok * 64 + 2 * lane] = make_float2(y0, y1);
        __syncwarp();
    }
}

// ---------------------------------------------------------------
// Phase 1.5: Gram lookahead. Warp per token; 8 four-lane groups,
// group j computes dot(k_t, k_{t-j}) over 16 elems/lane + 2 shfls.
// j=0 produces invd = 1/(||k||^2 + 1e-6) -> slot 7.
// j=1..7 -> slots 0..6 (0 when pos < j).
// ---------------------------------------------------------------
__global__ __launch_bounds__(256) void gram_kernel()
{
    const int wid  = (blockIdx.x * 256 + threadIdx.x) >> 5;
    const int lane = threadIdx.x & 31;
    if (wid >= NTOK) return;
    const int t   = wid;
    const int pos = t & (LSEQ - 1);
    const int j   = lane >> 2;     // 0..7
    const int sub = lane & 3;      // elems [sub*16, sub*16+16)

    const bool valid = (j == 0) || (pos >= j);
    const int  tm    = valid ? (t - j) : t;

    const ull* pa = (const ull*)&g_h[(size_t)t  * 64 + sub * 16];
    const ull* pb = (const ull*)&g_h[(size_t)tm * 64 + sub * 16];

    ull a0 = 0ull, a1 = 0ull, a2 = 0ull, a3 = 0ull;
    #pragma unroll
    for (int i = 0; i < 8; i += 4) {
        a0 = ffma2(pa[i],     pb[i],     a0);
        a1 = ffma2(pa[i + 1], pb[i + 1], a1);
        a2 = ffma2(pa[i + 2], pb[i + 2], a2);
        a3 = ffma2(pa[i + 3], pb[i + 3], a3);
    }
    float lo, hi;
    funpack2(fadd2(fadd2(a0, a1), fadd2(a2, a3)), lo, hi);
    float s = lo + hi;
    s += __shfl_xor_sync(0xffffffffu, s, 1);
    s += __shfl_xor_sync(0xffffffffu, s, 2);

    if (sub == 0) {
        if (j == 0) g_gram[(size_t)t * 8 + 7] = 1.0f / (s + 1e-6f);
        else        g_gram[(size_t)t * 8 + (j - 1)] = valid ? s : 0.0f;
    }
}

// ---------------------------------------------------------------
// Phase 2: delta-rule scan, rank-8 windows, pipelined dots.
// Grid 256 = 16 batches x 16 row-groups (4 rows); ONE warp per block.
// Thread (r, c8): row e = rg*4+r, cols [8*c8, 8*c8+8) (4 f32x2 regs).
// Window iteration:
//   serial: S_u = c_u + sum_{j<=u} dv_{u-j} g_j;  dv_u = ke_u - iv_u*S_u
//   update: M  += sum_u dv_u * kreg[u]        (k cached in regs from dots)
//   dots:   kreg[u] = k_{tb+8+u}; c_u = M . kreg[u]   (for next window)
//   prefetch tokens tb+24..31; __syncwarp.
// ---------------------------------------------------------------
__global__ __launch_bounds__(32, 1) void scan_kernel()
{
    __shared__ __align__(16) float smk[RING][64];
    __shared__ __align__(16) float smaux[RING][8];  // g1..g7, invd

    const int bb   = blockIdx.x >> 4;
    const int rg   = blockIdx.x & 15;
    const int tid  = threadIdx.x;   // 0..31
    const int r    = tid >> 3;      // row within group 0..3
    const int c8   = tid & 7;       // column eighth
    const int e    = rg * 4 + r;

    const float* __restrict__ hb  = g_h    + (size_t)bb * LSEQ * HD;
    const float* __restrict__ gga = g_gram + (size_t)bb * LSEQ * 8;

    // prologue: fill ring with tokens 0..23 (+aux)
    #pragma unroll
    for (int i = tid; i < 24 * 16; i += 32) {
        const int tok = i >> 4, seg = i & 15;
        *(float4*)&smk[tok][seg * 4] = *(const float4*)&hb[tok * 64 + seg * 4];
    }
    #pragma unroll
    for (int i = tid; i < 48; i += 32) {
        const int tok = i >> 1, hf = i & 1;
        *(float4*)&smaux[tok][hf * 4] = *(const float4*)&gga[tok * 8 + hf * 4];
    }
    __syncwarp();

    ull M[4];
    #pragma unroll
    for (int i = 0; i < 4; i++) M[i] = 0ull;

    ull kreg[8][4];
    #pragma unroll
    for (int u = 0; u < 8; u++) {     // tokens 0..7 for window 0's update
        const ulonglong2* kp = (const ulonglong2*)&smk[u][c8 * 8];
        const ulonglong2 k0 = kp[0], k1 = kp[1];
        kreg[u][0] = k0.x; kreg[u][1] = k0.y;
        kreg[u][2] = k1.x; kreg[u][3] = k1.y;
    }

    float c[8], dv[8];
    #pragma unroll
    for (int i = 0; i < 8; i++) c[i] = 0.0f;   // M_0 = 0

    #pragma unroll 1
    for (int tb = 0; tb <= 2032; tb += 8) {
        // ---- serial phase (window tb) ----
        #pragma unroll
        for (int u = 0; u < 8; u++) {
            const int sl = (tb + u) & (RING - 1);
            const float  ke = smk[sl][e];
            const float4 gA = *(const float4*)&smaux[sl][0];
            const float4 gB = *(const float4*)&smaux[sl][4];
            float S = c[u];
            if (u >= 7) S = fmaf(dv[u - 7], gB.z, S);
            if (u >= 6) S = fmaf(dv[u - 6], gB.y, S);
            if (u >= 5) S = fmaf(dv[u - 5], gB.x, S);
            if (u >= 4) S = fmaf(dv[u - 4], gA.w, S);
            if (u >= 3) S = fmaf(dv[u - 3], gA.z, S);
            if (u >= 2) S = fmaf(dv[u - 2], gA.y, S);
            if (u >= 1) S = fmaf(dv[u - 1], gA.x, S);
            dv[u] = fmaf(-gB.w, S, ke);
        }

        // ---- rank-8 M update (k from registers) ----
        #pragma unroll
        for (int u = 0; u < 8; u++) {
            const ull dvp = fpack2(dv[u], dv[u]);
            M[0] = ffma2(dvp, kreg[u][0], M[0]);
            M[1] = ffma2(dvp, kreg[u][1], M[1]);
            M[2] = ffma2(dvp, kreg[u][2], M[2]);
            M[3] = ffma2(dvp, kreg[u][3], M[3]);
        }

        // ---- dots for NEXT window: kreg[u] = k_{tb+8+u}; c_u = M . kreg[u] ----
        #pragma unroll
        for (int u = 0; u < 8; u++) {
            const ulonglong2* kd =
                (const ulonglong2*)&smk[(tb + 8 + u) & (RING - 1)][c8 * 8];
            const ulonglong2 k0 = kd[0], k1 = kd[1];
            kreg[u][0] = k0.x; kreg[u][1] = k0.y;
            kreg[u][2] = k1.x; kreg[u][3] = k1.y;
            ull a0 = ffma2(M[0], k0.x, 0ull);
            ull a1 = ffma2(M[1], k0.y, 0ull);
            a0 = ffma2(M[2], k1.x, a0);
            a1 = ffma2(M[3], k1.y, a1);
            float lo, hi;
            funpack2(fadd2(a0, a1), lo, hi);
            c[u] = lo + hi;
        }
        #pragma unroll
        for (int u = 0; u < 8; u++) c[u] += __shfl_xor_sync(0xffffffffu, c[u], 1);
        #pragma unroll
        for (int u = 0; u < 8; u++) c[u] += __shfl_xor_sync(0xffffffffu, c[u], 2);
        #pragma unroll
        for (int u = 0; u < 8; u++) c[u] += __shfl_xor_sync(0xffffffffu, c[u], 4);

        // ---- prefetch tokens tb+24 .. tb+31 (pad-safe) ----
        #pragma unroll
        for (int w = 0; w < 4; w++) {
            const int i = w * 32 + tid;
            const int tok = tb + 24 + (i >> 4);
            const int seg = i & 15;
            *(float4*)&smk[tok & (RING - 1)][seg * 4] =
                *(const float4*)&hb[tok * 64 + seg * 4];
        }
        if (tid < 16) {
            const int tok = tb + 24 + (tid >> 1);
            const int hf  = tid & 1;
            *(float4*)&smaux[tok & (RING - 1)][hf * 4] =
                *(const float4*)&gga[tok * 8 + hf * 4];
        }
        __syncwarp();
    }

    // ---- tail window tb=2040: 7 serial steps, then ctx at token 2047 ----
    {
        const int tb = 2040;
        #pragma unroll
        for (int u = 0; u < 7; u++) {
            const int sl = (tb + u) & (RING - 1);
            const float  ke = smk[sl][e];
            const float4 gA = *(const float4*)&smaux[sl][0];
            const float4 gB = *(const float4*)&smaux[sl][4];
            float S = c[u];
            if (u >= 6) S = fmaf(dv[u - 6], gB.y, S);
            if (u >= 5) S = fmaf(dv[u - 5], gB.x, S);
            if (u >= 4) S = fmaf(dv[u - 4], gA.w, S);
            if (u >= 3) S = fmaf(dv[u - 3], gA.z, S);
            if (u >= 2) S = fmaf(dv[u - 2], gA.y, S);
            if (u >= 1) S = fmaf(dv[u - 1], gA.x, S);
            dv[u] = fmaf(-gB.w, S, ke);
        }

        // ctx[e] = c_7 + sum_{j=1..7} dv_{7-j} * g_j[2047]
        const float4 gA = *(const float4*)&smaux[2047 & (RING - 1)][0];
        const float4 gB = *(const float4*)&smaux[2047 & (RING - 1)][4];
        float S = c[7];
        S = fmaf(dv[0], gB.z, S);
        S = fmaf(dv[1], gB.y, S);
        S = fmaf(dv[2], gB.x, S);
        S = fmaf(dv[3], gA.w, S);
        S = fmaf(dv[4], gA.z, S);
        S = fmaf(dv[5], gA.y, S);
        S = fmaf(dv[6], gA.x, S);
        if (c8 == 0) g_ctx[bb * 64 + e] = S;
    }
}

// ---------------------------------------------------------------
// Phase 3: out = (ctx @ Wr + br) @ Wo + bo
// ---------------------------------------------------------------
__global__ __launch_bounds__(64) void proj_kernel(
    const float* __restrict__ Wr, const float* __restrict__ br,
    const float* __restrict__ Wo, const float* __restrict__ bo,
    float* __restrict__ out)
{
    __shared__ float cs[64], rs[64];
    const int b   = blockIdx.x;
    const int tid = threadIdx.x;
    cs[tid] = g_ctx[b * 64 + tid];
    __syncthreads();
    float rr = br[tid];
    #pragma unroll 8
    for (int j = 0; j < 64; j++) rr = fmaf(cs[j], Wr[j * 64 + tid], rr);
    rs[tid] = rr;
    __syncthreads();
    float o = bo[tid];
    #pragma unroll 8
    for (int j = 0; j < 64; j++) o = fmaf(rs[j], Wo[j * 64 + tid], o);
    out[b * 64 + tid] = o;
}

// ---------------------------------------------------------------
extern "C" void kernel_launch(void* const* d_in, const int* in_sizes, int n_in,
                              void* d_out, int out_size)
{
    const int*   seq   = (const int*)  d_in[0];
    const float* embed = (const float*)d_in[1];
    const float* W1    = (const float*)d_in[2];
    const float* b1    = (const float*)d_in[3];
    const float* W2    = (const float*)d_in[4];
    const float* b2    = (const float*)d_in[5];
    const float* gamma = (const float*)d_in[6];
    const float* beta  = (const float*)d_in[7];
    const float* Wr    = (const float*)d_in[8];
    const float* br    = (const float*)d_in[9];
    const float* Wo    = (const float*)d_in[10];
    const float* bo    = (const float*)d_in[11];
    float* out = (float*)d_out;

    (void)in_sizes; (void)n_in; (void)out_size;

    cudaFuncSetAttribute(phase1_kernel,
                         cudaFuncAttributeMaxDynamicSharedMemorySize, 65536);
    phase1_kernel<<<296, 256, 65536>>>(seq, embed, W1, b1, W2, b2, gamma, beta);
    gram_kernel<<<NTOK / 8, 256>>>();
    scan_kernel<<<BATCH * 16, 32>>>();
    proj_kernel<<<BATCH, 64>>>(Wr, br, Wo, bo, out);
}

// round 13
// speedup vs baseline: 6.5908x; 1.2251x over previous
#include <cuda_runtime.h>

#define HD    64
#define LSEQ  2048
#define BATCH 16
#define NTOK  (BATCH * LSEQ)
#define RING  32

typedef unsigned long long ull;

// Scratch (device globals, zero-initialized; pad regions never written -> stay 0)
__device__ float g_h[(NTOK + 16) * HD];   // post-LN hidden states (+pad)
__device__ float g_gram[(NTOK + 16) * 8]; // per token: g_1..g_7 (g_j = k_{t-j}.k_t), invd
__device__ float g_ctx[BATCH * HD];       // ctx = M_final . q

// ---------------- packed f32x2 helpers (sm_103a) ----------------
__device__ __forceinline__ ull ffma2(ull a, ull b, ull c) {
    ull d;
    asm("fma.rn.f32x2 %0, %1, %2, %3;" : "=l"(d) : "l"(a), "l"(b), "l"(c));
    return d;
}
__device__ __forceinline__ ull fadd2(ull a, ull b) {
    ull d;
    asm("add.rn.f32x2 %0, %1, %2;" : "=l"(d) : "l"(a), "l"(b));
    return d;
}
__device__ __forceinline__ ull fmul2(ull a, ull b) {
    ull d;
    asm("mul.rn.f32x2 %0, %1, %2;" : "=l"(d) : "l"(a), "l"(b));
    return d;
}
__device__ __forceinline__ ull fpack2(float lo, float hi) {
    ull d;
    asm("mov.b64 %0, {%1, %2};" : "=l"(d) : "f"(lo), "f"(hi));
    return d;
}
__device__ __forceinline__ void funpack2(ull v, float& lo, float& hi) {
    asm("mov.b64 {%0, %1}, %2;" : "=f"(lo), "=f"(hi) : "l"(v));
}
__device__ __forceinline__ ull fdup2(float x) { return fpack2(x, x); }

// ---------------------------------------------------------------
// Phase 1 (v2): register-blocked packed MLP+LN.
// 8 warps/block; each warp processes an 8-token tile.
// Tokens packed in pairs into f32x2; weights fetched once per row
// and reused across all 8 tokens of the tile.
// ---------------------------------------------------------------
#define HP_STRIDE 10   // pad: row stride (floats) for h tile
#define AP_STRIDE 10   // pad: row stride (floats) for activation tile

__global__ __launch_bounds__(256) void phase1_kernel(
    const int*   __restrict__ seq,
    const float* __restrict__ embed,
    const float* __restrict__ W1,
    const float* __restrict__ b1,
    const float* __restrict__ W2,
    const float* __restrict__ b2,
    const float* __restrict__ gamma,
    const float* __restrict__ beta)
{
    extern __shared__ float dsm[];
    float* W1s = dsm;            // 64*128
    float* W2s = dsm + 64 * 128; // 128*64

    __shared__ __align__(16) float b1s[128];
    __shared__ float b2s[64], gs[64], bs[64];
    __shared__ __align__(8) float hpf[8][64][HP_STRIDE];   // h tile  [dim][token]
    __shared__ __align__(8) float apf[8][128][AP_STRIDE];  // act tile [m][token]

    const int tid = threadIdx.x;
    for (int i = tid; i < 64 * 128; i += 256) W1s[i] = W1[i];
    for (int i = tid; i < 128 * 64; i += 256) W2s[i] = W2[i];
    if (tid < 128) b1s[tid] = b1[tid];
    if (tid < 64) { b2s[tid] = b2[tid]; gs[tid] = gamma[tid]; bs[tid] = beta[tid]; }
    __syncthreads();

    const int w    = tid >> 5;
    const int lane = tid & 31;
    const int gw   = blockIdx.x * 8 + w;     // global warp id
    const int nw   = gridDim.x * 8;

    const ull negone = fdup2(-1.0f);
    const ull inv64  = fdup2(1.0f / 64.0f);

    for (int tile = gw; tile < NTOK / 8; tile += nw) {
        const int tok0 = tile * 8;

        // ---- gather: hpf[j][tt] = embed[seq[tok0+tt]][j] ----
        #pragma unroll
        for (int tt = 0; tt < 8; tt++) {
            const int v = seq[tok0 + tt];
            hpf[w][lane][tt]      = embed[v * 64 + lane];
            hpf[w][lane + 32][tt] = embed[v * 64 + 32 + lane];
        }
        __syncwarp();

        // ---- layer 1: a[m] = relu(sum_j h[j]*W1[j,m] + b1[m]) ----
        // lane owns outputs m = 4*lane..+3; acc[p][o] packs token pair p.
        ull acc[4][4];
        {
            const float4 bb4 = *(const float4*)&b1s[lane * 4];
            #pragma unroll
            for (int p = 0; p < 4; p++) {
                acc[p][0] = fdup2(bb4.x); acc[p][1] = fdup2(bb4.y);
                acc[p][2] = fdup2(bb4.z); acc[p][3] = fdup2(bb4.w);
            }
        }
        #pragma unroll 8
        for (int j = 0; j < 64; j++) {
            const float4 w4 = *(const float4*)&W1s[j * 128 + lane * 4];
            const ull wd0 = fdup2(w4.x), wd1 = fdup2(w4.y);
            const ull wd2 = fdup2(w4.z), wd3 = fdup2(w4.w);
            #pragma unroll
            for (int p = 0; p < 4; p++) {
                const ull hj = *(const ull*)&hpf[w][j][2 * p];  // broadcast
                acc[p][0] = ffma2(hj, wd0, acc[p][0]);
                acc[p][1] = ffma2(hj, wd1, acc[p][1]);
                acc[p][2] = ffma2(hj, wd2, acc[p][2]);
                acc[p][3] = ffma2(hj, wd3, acc[p][3]);
            }
        }
        // relu + store activations
        #pragma unroll
        for (int p = 0; p < 4; p++)
            #pragma unroll
            for (int o = 0; o < 4; o++) {
                float lo, hi;
                funpack2(acc[p][o], lo, hi);
                *(ull*)&apf[w][lane * 4 + o][2 * p] =
                    fpack2(fmaxf(lo, 0.f), fmaxf(hi, 0.f));
            }
        __syncwarp();

        // ---- layer 2: f[i] = sum_m a[m]*W2[m,i] + b2[i]; lane owns i=2l,2l+1 ----
        ull a2[2][4];
        {
            const float2 bb2 = *(const float2*)&b2s[2 * lane];
            #pragma unroll
            for (int p = 0; p < 4; p++) {
                a2[0][p] = fdup2(bb2.x);
                a2[1][p] = fdup2(bb2.y);
            }
        }
        #pragma unroll 8
        for (int m = 0; m < 128; m++) {
            const float2 w2 = *(const float2*)&W2s[m * 64 + 2 * lane];
            const ull wd0 = fdup2(w2.x), wd1 = fdup2(w2.y);
            #pragma unroll
            for (int p = 0; p < 4; p++) {
                const ull am = *(const ull*)&apf[w][m][2 * p];  // broadcast
                a2[0][p] = ffma2(am, wd0, a2[0][p]);
                a2[1][p] = ffma2(am, wd1, a2[1][p]);
            }
        }

        // ---- residual + LayerNorm (packed over token pairs) ----
        ull xp[2][4];
        #pragma unroll
        for (int o = 0; o < 2; o++)
            #pragma unroll
            for (int p = 0; p < 4; p++) {
                const ull hv = *(const ull*)&hpf[w][2 * lane + o][2 * p];
                xp[o][p] = fadd2(a2[o][p], hv);
            }

        // mean over 64 dims per token (packed pair reduce)
        ull mu2[4], rstd2[4];
        #pragma unroll
        for (int p = 0; p < 4; p++) {
            ull s = fadd2(xp[0][p], xp[1][p]);
            #pragma unroll
            for (int off = 16; off > 0; off >>= 1) {
                float lo, hi;
                funpack2(s, lo, hi);
                lo += __shfl_xor_sync(0xffffffffu, lo, off);
                hi += __shfl_xor_sync(0xffffffffu, hi, off);
                s = fpack2(lo, hi);
            }
            mu2[p] = fmul2(s, inv64);
        }
        // variance
        #pragma unroll
        for (int p = 0; p < 4; p++) {
            const ull d0 = ffma2(mu2[p], negone, xp[0][p]);
            const ull d1 = ffma2(mu2[p], negone, xp[1][p]);
            ull s = fadd2(ffma2(d0, d0, 0ull), ffma2(d1, d1, 0ull));
            #pragma unroll
            for (int off = 16; off > 0; off >>= 1) {
                float lo, hi;
                funpack2(s, lo, hi);
                lo += __shfl_xor_sync(0xffffffffu, lo, off);
                hi += __shfl_xor_sync(0xffffffffu, hi, off);
                s = fpack2(lo, hi);
            }
            float vlo, vhi;
            funpack2(fmul2(s, inv64), vlo, vhi);
            rstd2[p] = fpack2(rsqrtf(vlo + 1e-5f), rsqrtf(vhi + 1e-5f));
        }
        // y = (x - mu) * rstd * gamma + beta; scatter to g_h
        #pragma unroll
        for (int o = 0; o < 2; o++) {
            const ull gm = fdup2(gs[2 * lane + o]);
            const ull bt = fdup2(bs[2 * lane + o]);
            #pragma unroll
            for (int p = 0; p < 4; p++) {
                const ull d  = ffma2(mu2[p], negone, xp[o][p]);
                const ull t  = fmul2(fmul2(d, rstd2[p]), gm);
                const ull y  = fadd2(t, bt);
                float lo, hi;
                funpack2(y, lo, hi);
                g_h[(tok0 + 2 * p)     * 64 + 2 * lane + o] = lo;
                g_h[(tok0 + 2 * p + 1) * 64 + 2 * lane + o] = hi;
            }
        }
        __syncwarp();
    }
}

// ---------------------------------------------------------------
// Phase 1.5: Gram lookahead. Warp per token; 8 four-lane groups,
// group j computes dot(k_t, k_{t-j}); j=0 -> invd in slot 7.
// ---------------------------------------------------------------
__global__ __launch_bounds__(256) void gram_kernel()
{
    const int wid  = (blockIdx.x * 256 + threadIdx.x) >> 5;
    const int lane = threadIdx.x & 31;
    if (wid >= NTOK) return;
    const int t   = wid;
    const int pos = t & (LSEQ - 1);
    const int j   = lane >> 2;     // 0..7
    const int sub = lane & 3;      // elems [sub*16, sub*16+16)

    const bool valid = (j == 0) || (pos >= j);
    const int  tm    = valid ? (t - j) : t;

    const ull* pa = (const ull*)&g_h[(size_t)t  * 64 + sub * 16];
    const ull* pb = (const ull*)&g_h[(size_t)tm * 64 + sub * 16];

    ull a0 = 0ull, a1 = 0ull, a2 = 0ull, a3 = 0ull;
    #pragma unroll
    for (int i = 0; i < 8; i += 4) {
        a0 = ffma2(pa[i],     pb[i],     a0);
        a1 = ffma2(pa[i + 1], pb[i + 1], a1);
        a2 = ffma2(pa[i + 2], pb[i + 2], a2);
        a3 = ffma2(pa[i + 3], pb[i + 3], a3);
    }
    float lo, hi;
    funpack2(fadd2(fadd2(a0, a1), fadd2(a2, a3)), lo, hi);
    float s = lo + hi;
    s += __shfl_xor_sync(0xffffffffu, s, 1);
    s += __shfl_xor_sync(0xffffffffu, s, 2);

    if (sub == 0) {
        if (j == 0) g_gram[(size_t)t * 8 + 7] = 1.0f / (s + 1e-6f);
        else        g_gram[(size_t)t * 8 + (j - 1)] = valid ? s : 0.0f;
    }
}

// ---------------------------------------------------------------
// Phase 2: delta-rule scan, rank-8 windows, pipelined dots.
// (unchanged from round 12 — current best)
// ---------------------------------------------------------------
__global__ __launch_bounds__(32, 1) void scan_kernel()
{
    __shared__ __align__(16) float smk[RING][64];
    __shared__ __align__(16) float smaux[RING][8];  // g1..g7, invd

    const int bb   = blockIdx.x >> 4;
    const int rg   = blockIdx.x & 15;
    const int tid  = threadIdx.x;   // 0..31
    const int r    = tid >> 3;      // row within group 0..3
    const int c8   = tid & 7;       // column eighth
    const int e    = rg * 4 + r;

    const float* __restrict__ hb  = g_h    + (size_t)bb * LSEQ * HD;
    const float* __restrict__ gga = g_gram + (size_t)bb * LSEQ * 8;

    #pragma unroll
    for (int i = tid; i < 24 * 16; i += 32) {
        const int tok = i >> 4, seg = i & 15;
        *(float4*)&smk[tok][seg * 4] = *(const float4*)&hb[tok * 64 + seg * 4];
    }
    #pragma unroll
    for (int i = tid; i < 48; i += 32) {
        const int tok = i >> 1, hf = i & 1;
        *(float4*)&smaux[tok][hf * 4] = *(const float4*)&gga[tok * 8 + hf * 4];
    }
    __syncwarp();

    ull M[4];
    #pragma unroll
    for (int i = 0; i < 4; i++) M[i] = 0ull;

    ull kreg[8][4];
    #pragma unroll
    for (int u = 0; u < 8; u++) {
        const ulonglong2* kp = (const ulonglong2*)&smk[u][c8 * 8];
        const ulonglong2 k0 = kp[0], k1 = kp[1];
        kreg[u][0] = k0.x; kreg[u][1] = k0.y;
        kreg[u][2] = k1.x; kreg[u][3] = k1.y;
    }

    float c[8], dv[8];
    #pragma unroll
    for (int i = 0; i < 8; i++) c[i] = 0.0f;

    #pragma unroll 1
    for (int tb = 0; tb <= 2032; tb += 8) {
        #pragma unroll
        for (int u = 0; u < 8; u++) {
            const int sl = (tb + u) & (RING - 1);
            const float  ke = smk[sl][e];
            const float4 gA = *(const float4*)&smaux[sl][0];
            const float4 gB = *(const float4*)&smaux[sl][4];
            float S = c[u];
            if (u >= 7) S = fmaf(dv[u - 7], gB.z, S);
            if (u >= 6) S = fmaf(dv[u - 6], gB.y, S);
            if (u >= 5) S = fmaf(dv[u - 5], gB.x, S);
            if (u >= 4) S = fmaf(dv[u - 4], gA.w, S);
            if (u >= 3) S = fmaf(dv[u - 3], gA.z, S);
            if (u >= 2) S = fmaf(dv[u - 2], gA.y, S);
            if (u >= 1) S = fmaf(dv[u - 1], gA.x, S);
            dv[u] = fmaf(-gB.w, S, ke);
        }

        #pragma unroll
        for (int u = 0; u < 8; u++) {
            const ull dvp = fpack2(dv[u], dv[u]);
            M[0] = ffma2(dvp, kreg[u][0], M[0]);
            M[1] = ffma2(dvp, kreg[u][1], M[1]);
            M[2] = ffma2(dvp, kreg[u][2], M[2]);
            M[3] = ffma2(dvp, kreg[u][3], M[3]);
        }

        #pragma unroll
        for (int u = 0; u < 8; u++) {
            const ulonglong2* kd =
                (const ulonglong2*)&smk[(tb + 8 + u) & (RING - 1)][c8 * 8];
            const ulonglong2 k0 = kd[0], k1 = kd[1];
            kreg[u][0] = k0.x; kreg[u][1] = k0.y;
            kreg[u][2] = k1.x; kreg[u][3] = k1.y;
            ull a0 = ffma2(M[0], k0.x, 0ull);
            ull a1 = ffma2(M[1], k0.y, 0ull);
            a0 = ffma2(M[2], k1.x, a0);
            a1 = ffma2(M[3], k1.y, a1);
            float lo, hi;
            funpack2(fadd2(a0, a1), lo, hi);
            c[u] = lo + hi;
        }
        #pragma unroll
        for (int u = 0; u < 8; u++) c[u] += __shfl_xor_sync(0xffffffffu, c[u], 1);
        #pragma unroll
        for (int u = 0; u < 8; u++) c[u] += __shfl_xor_sync(0xffffffffu, c[u], 2);
        #pragma unroll
        for (int u = 0; u < 8; u++) c[u] += __shfl_xor_sync(0xffffffffu, c[u], 4);

        #pragma unroll
        for (int w = 0; w < 4; w++) {
            const int i = w * 32 + tid;
            const int tok = tb + 24 + (i >> 4);
            const int seg = i & 15;
            *(float4*)&smk[tok & (RING - 1)][seg * 4] =
                *(const float4*)&hb[tok * 64 + seg * 4];
        }
        if (tid < 16) {
            const int tok = tb + 24 + (tid >> 1);
            const int hf  = tid & 1;
            *(float4*)&smaux[tok & (RING - 1)][hf * 4] =
                *(const float4*)&gga[tok * 8 + hf * 4];
        }
        __syncwarp();
    }

    {
        const int tb = 2040;
        #pragma unroll
        for (int u = 0; u < 7; u++) {
            const int sl = (tb + u) & (RING - 1);
            const float  ke = smk[sl][e];
            const float4 gA = *(const float4*)&smaux[sl][0];
            const float4 gB = *(const float4*)&smaux[sl][4];
            float S = c[u];
            if (u >= 6) S = fmaf(dv[u - 6], gB.y, S);
            if (u >= 5) S = fmaf(dv[u - 5], gB.x, S);
            if (u >= 4) S = fmaf(dv[u - 4], gA.w, S);
            if (u >= 3) S = fmaf(dv[u - 3], gA.z, S);
            if (u >= 2) S = fmaf(dv[u - 2], gA.y, S);
            if (u >= 1) S = fmaf(dv[u - 1], gA.x, S);
            dv[u] = fmaf(-gB.w, S, ke);
        }

        const float4 gA = *(const float4*)&smaux[2047 & (RING - 1)][0];
        const float4 gB = *(const float4*)&smaux[2047 & (RING - 1)][4];
        float S = c[7];
        S = fmaf(dv[0], gB.z, S);
        S = fmaf(dv[1], gB.y, S);
        S = fmaf(dv[2], gB.x, S);
        S = fmaf(dv[3], gA.w, S);
        S = fmaf(dv[4], gA.z, S);
        S = fmaf(dv[5], gA.y, S);
        S = fmaf(dv[6], gA.x, S);
        if (c8 == 0) g_ctx[bb * 64 + e] = S;
    }
}

// ---------------------------------------------------------------
// Phase 3: out = (ctx @ Wr + br) @ Wo + bo
// ---------------------------------------------------------------
__global__ __launch_bounds__(64) void proj_kernel(
    const float* __restrict__ Wr, const float* __restrict__ br,
    const float* __restrict__ Wo, const float* __restrict__ bo,
    float* __restrict__ out)
{
    __shared__ float cs[64], rs[64];
    const int b   = blockIdx.x;
    const int tid = threadIdx.x;
    cs[tid] = g_ctx[b * 64 + tid];
    __syncthreads();
    float rr = br[tid];
    #pragma unroll 8
    for (int j = 0; j < 64; j++) rr = fmaf(cs[j], Wr[j * 64 + tid], rr);
    rs[tid] = rr;
    __syncthreads();
    float o = bo[tid];
    #pragma unroll 8
    for (int j = 0; j < 64; j++) o = fmaf(rs[j], Wo[j * 64 + tid], o);
    out[b * 64 + tid] = o;
}

// ---------------------------------------------------------------
extern "C" void kernel_launch(void* const* d_in, const int* in_sizes, int n_in,
                              void* d_out, int out_size)
{
    const int*   seq   = (const int*)  d_in[0];
    const float* embed = (const float*)d_in[1];
    const float* W1    = (const float*)d_in[2];
    const float* b1    = (const float*)d_in[3];
    const float* W2    = (const float*)d_in[4];
    const float* b2    = (const float*)d_in[5];
    const float* gamma = (const float*)d_in[6];
    const float* beta  = (const float*)d_in[7];
    const float* Wr    = (const float*)d_in[8];
    const float* br    = (const float*)d_in[9];
    const float* Wo    = (const float*)d_in[10];
    const float* bo    = (const float*)d_in[11];
    float* out = (float*)d_out;

    (void)in_sizes; (void)n_in; (void)out_size;

    cudaFuncSetAttribute(phase1_kernel,
                         cudaFuncAttributeMaxDynamicSharedMemorySize, 65536);
    phase1_kernel<<<256, 256, 65536>>>(seq, embed, W1, b1, W2, b2, gamma, beta);
    gram_kernel<<<NTOK / 8, 256>>>();
    scan_kernel<<<BATCH * 16, 32>>>();
    proj_kernel<<<BATCH, 64>>>(Wr, br, Wo, bo, out);
}